// round 13
// baseline (speedup 1.0000x reference)
#include <cuda_runtime.h>
#include <cuda_bf16.h>
#include <math.h>

#define Bz   2
#define Cd   256
#define Hh   40
#define Wd   40
#define HW   1600
#define TOK  3200
#define NHd  8
#define HDd  32
#define WSd  15
#define W2Sd 225
#define MDd  7
#define HIDd 1024
#define GNg  32
#define EPSf 1e-5f
#define NEGINF -1e38f

// attention tiling (round-10 champion layout)
#define QT    4
#define EXT   18
#define EXT2  (EXT*EXT)
#define KPAD  325          // bf16x2 row stride (channel-pair rows)
#define SPAD  228
#define RELP  236

// GEMM tiling
#define BN 64
#define BK 32
#define KP 36

// ---------------- scratch ----------------
__device__ float g_qln[TOK*Cd];
__device__ float g_kln[TOK*Cd];
__device__ float g_vln[TOK*Cd];
__device__ float g_Q[TOK*Cd];
__device__ float g_K[TOK*Cd];
__device__ float g_V[TOK*Cd];
__device__ float g_att[TOK*Cd];
__device__ float g_x1[TOK*Cd];
__device__ float g_ln2[TOK*Cd];
__device__ float g_h1[TOK*HIDd];
__device__ float g_cv[TOK*HIDd];
__device__ float g_gnm[Bz*GNg*2];

// ---------------- block mean/var helper (256 threads) ----------------
__device__ __forceinline__ void block_meanvar(float v, float* sbuf,
                                              float& mu, float& rstd) {
    float s = v, q = v*v;
    #pragma unroll
    for (int d = 16; d > 0; d >>= 1) {
        s += __shfl_xor_sync(0xffffffffu, s, d);
        q += __shfl_xor_sync(0xffffffffu, q, d);
    }
    int warp = threadIdx.x >> 5, lane = threadIdx.x & 31;
    if (lane == 0) { sbuf[warp] = s; sbuf[8 + warp] = q; }
    __syncthreads();
    if (warp == 0) {
        float ss = (lane < 8) ? sbuf[lane] : 0.f;
        float qq = (lane < 8) ? sbuf[8 + lane] : 0.f;
        #pragma unroll
        for (int d = 4; d > 0; d >>= 1) {
            ss += __shfl_xor_sync(0xffffffffu, ss, d);
            qq += __shfl_xor_sync(0xffffffffu, qq, d);
        }
        if (lane == 0) {
            float m = ss * (1.0f/Cd);
            float var = qq * (1.0f/Cd) - m*m;
            sbuf[16] = m;
            sbuf[17] = rsqrtf(var + EPSf);
        }
    }
    __syncthreads();
    mu = sbuf[16]; rstd = sbuf[17];
}

// ---------------- fused LN of img / img_warp / img_warp+mask ----------------
__global__ void ln3_kernel(const float* __restrict__ img,
                           const float* __restrict__ imw,
                           const float* __restrict__ msk,
                           const float* __restrict__ g1,
                           const float* __restrict__ b1) {
    int tok = blockIdx.x;
    int c   = threadIdx.x;
    int b   = tok / HW, pos = tok % HW;
    int off = (b*Cd + c)*HW + pos;

    float x0 = img[off];
    float x1 = imw[off];
    float x2 = x1 + msk[off];
    float gg = g1[c], bb = b1[c];

    __shared__ float sbuf[18];
    float mu, rs;

    block_meanvar(x0, sbuf, mu, rs);
    g_qln[tok*Cd + c] = (x0 - mu) * rs * gg + bb;
    __syncthreads();
    block_meanvar(x1, sbuf, mu, rs);
    g_kln[tok*Cd + c] = (x1 - mu) * rs * gg + bb;
    __syncthreads();
    block_meanvar(x2, sbuf, mu, rs);
    g_vln[tok*Cd + c] = (x2 - mu) * rs * gg + bb;
}

__global__ void ln_tok_kernel(const float* __restrict__ g1,
                              const float* __restrict__ b1) {
    int tok = blockIdx.x;
    int c   = threadIdx.x;
    float v = g_x1[tok*Cd + c];
    __shared__ float sbuf[18];
    float mu, rs;
    block_meanvar(v, sbuf, mu, rs);
    g_ln2[tok*Cd + c] = (v - mu) * rs * g1[c] + b1[c];
}

// ---------------- tf32 helpers ----------------
__device__ __forceinline__ unsigned f2tf32(float x) {
    unsigned r;
    asm("cvt.rna.tf32.f32 %0, %1;" : "=r"(r) : "f"(x));
    return r;
}
__device__ __forceinline__ void mma_tf32(float& c0, float& c1, float& c2, float& c3,
                                         unsigned a0, unsigned a1, unsigned a2, unsigned a3,
                                         unsigned b0, unsigned b1) {
    asm volatile(
        "mma.sync.aligned.m16n8k8.row.col.f32.tf32.tf32.f32 "
        "{%0,%1,%2,%3}, {%4,%5,%6,%7}, {%8,%9}, {%0,%1,%2,%3};"
        : "+f"(c0), "+f"(c1), "+f"(c2), "+f"(c3)
        : "r"(a0), "r"(a1), "r"(a2), "r"(a3), "r"(b0), "r"(b1));
}
__device__ __forceinline__ void cp_async16(unsigned dst, const void* src) {
    asm volatile("cp.async.cg.shared.global [%0], [%1], 16;\n"
                 :: "r"(dst), "l"(src));
}
__device__ __forceinline__ void cp_commit() {
    asm volatile("cp.async.commit_group;\n");
}

// ---------------- tf32 GEMM, cp.async double buffered, optional split-K ----
// mode 0: C[m*N+n] = v                                   (store, no split)
// mode 1: atomicAdd C[m*N+n] += v (+bias+img res if lead)
// mode 2: atomicAdd out[(b*Cd+n)*HW+pos] += v (+bias+res if lead)
template<int BMT>
__device__ __forceinline__ void mma_body(const float* __restrict__ A, int lda,
                                         const float* __restrict__ Wt, int ldw,
                                         const float* __restrict__ bias,
                                         float* __restrict__ C,
                                         int N, int Kloop, int m0, int n0,
                                         int mode, const float* __restrict__ res,
                                         bool lead, bool atomic) {
    constexpr int MT = BMT / 64;
    extern __shared__ float smem[];
    float* As = smem;
    float* Ws = smem + 2*BMT*KP;

    int tid  = threadIdx.x;
    int lane = tid & 31, warp = tid >> 5;
    int wm = (warp >> 1) * (16*MT), wn = (warp & 1) * 32;
    int g = lane >> 2, t4 = lane & 3;

    float acc[MT][4][4] = {};
    int steps = Kloop / BK;

    unsigned sA = (unsigned)__cvta_generic_to_shared(As);
    unsigned sW = (unsigned)__cvta_generic_to_shared(Ws);

    auto load_stage = [&](int kc, int s) {
        int k0 = kc * BK;
        #pragma unroll
        for (int it = 0; it < BMT/32; it++) {
            int idx = tid + it*256;
            int row = idx >> 3, ch = (idx & 7) * 4;
            cp_async16(sA + (unsigned)(((s*BMT + row)*KP + ch) * 4),
                       &A[(size_t)(m0+row)*lda + k0 + ch]);
        }
        #pragma unroll
        for (int it = 0; it < 2; it++) {
            int idx = tid + it*256;
            int row = idx >> 3, ch = (idx & 7) * 4;
            cp_async16(sW + (unsigned)(((s*BN + row)*KP + ch) * 4),
                       &Wt[(size_t)(n0+row)*ldw + k0 + ch]);
        }
        cp_commit();
    };

    load_stage(0, 0);

    for (int kc = 0; kc < steps; kc++) {
        int s = kc & 1;
        if (kc + 1 < steps) {
            load_stage(kc + 1, (kc + 1) & 1);
            asm volatile("cp.async.wait_group 1;\n");
        } else {
            asm volatile("cp.async.wait_group 0;\n");
        }
        __syncthreads();

        float* Ab = As + s*BMT*KP;
        float* Wb = Ws + s*BN*KP;
        #pragma unroll
        for (int ks = 0; ks < BK; ks += 8) {
            unsigned a[MT][4], bf[4][2];
            #pragma unroll
            for (int mt = 0; mt < MT; mt++) {
                int rb = wm + mt*16;
                a[mt][0] = f2tf32(Ab[(rb + g    )*KP + ks + t4    ]);
                a[mt][1] = f2tf32(Ab[(rb + g + 8)*KP + ks + t4    ]);
                a[mt][2] = f2tf32(Ab[(rb + g    )*KP + ks + t4 + 4]);
                a[mt][3] = f2tf32(Ab[(rb + g + 8)*KP + ks + t4 + 4]);
            }
            #pragma unroll
            for (int nt = 0; nt < 4; nt++) {
                int nb = wn + nt*8 + g;
                bf[nt][0] = f2tf32(Wb[nb*KP + ks + t4    ]);
                bf[nt][1] = f2tf32(Wb[nb*KP + ks + t4 + 4]);
            }
            #pragma unroll
            for (int mt = 0; mt < MT; mt++)
                #pragma unroll
                for (int nt = 0; nt < 4; nt++)
                    mma_tf32(acc[mt][nt][0], acc[mt][nt][1],
                             acc[mt][nt][2], acc[mt][nt][3],
                             a[mt][0], a[mt][1], a[mt][2], a[mt][3],
                             bf[nt][0], bf[nt][1]);
        }
        __syncthreads();
    }

    #pragma unroll
    for (int mt = 0; mt < MT; mt++) {
        #pragma unroll
        for (int nt = 0; nt < 4; nt++) {
            #pragma unroll
            for (int i = 0; i < 4; i++) {
                int mrow = m0 + wm + mt*16 + g + ((i >= 2) ? 8 : 0);
                int ncol = n0 + wn + nt*8 + 2*t4 + (i & 1);
                float v = acc[mt][nt][i] + (lead ? bias[ncol] : 0.f);
                if (mode == 0) {
                    C[(size_t)mrow*N + ncol] = v;
                } else if (mode == 1) {
                    int b = mrow / HW, pos = mrow % HW;
                    if (lead) v += res[(size_t)(b*Cd + ncol)*HW + pos];
                    if (atomic) atomicAdd(&C[(size_t)mrow*N + ncol], v);
                    else        C[(size_t)mrow*N + ncol] = v;
                } else {
                    int b = mrow / HW, pos = mrow % HW;
                    if (lead) v += res[(size_t)mrow*N + ncol];
                    if (atomic) atomicAdd(&C[(size_t)(b*Cd + ncol)*HW + pos], v);
                    else        C[(size_t)(b*Cd + ncol)*HW + pos] = v;
                }
            }
        }
    }
}

template<int BMT>
__global__ void mma_gemm_kernel(const float* __restrict__ A,
                                const float* __restrict__ Wt,
                                const float* __restrict__ bias,
                                float* __restrict__ C,
                                int N, int K, int mode,
                                const float* __restrict__ res) {
    int z = blockIdx.z, zc = gridDim.z;
    int Ks = K / zc;
    mma_body<BMT>(A + z*Ks, K, Wt + z*Ks, K, bias, C, N, Ks,
                  blockIdx.y*BMT, blockIdx.x*BN, mode, res,
                  z == 0, zc > 1);
}

struct QKVArgs {
    const float* A[3];
    const float* W[3];
    const float* bias[3];
    float* C[3];
};
__global__ void mma_qkv_kernel(QKVArgs args) {
    int z = blockIdx.z;
    mma_body<128>(args.A[z], Cd, args.W[z], Cd, args.bias[z], args.C[z],
                  Cd, Cd, blockIdx.y*128, blockIdx.x*BN, 0, nullptr,
                  true, false);
}

// ---------------- tiled local attention (round-10 champion) ----------------
__global__ void attn_tile_kernel(const float* __restrict__ Wrel,
                                 const float* __restrict__ brel) {
    extern __shared__ float smem[];
    __nv_bfloat162* sKh = (__nv_bfloat162*)smem;   // [16 c2][KPAD]  K then V
    float* sS   = smem + 16*KPAD;                  // [16][SPAD]
    float* sRel = sS + 16*SPAD;                    // [16][RELP]
    float* sInv = sRel + 16*RELP;                  // [16]
    float* sbr  = sInv + 16;                       // [228]

    int tile = blockIdx.x;
    int h = blockIdx.y, b = blockIdx.z;
    int ty0 = (tile / (Wd/QT)) * QT;
    int tx0 = (tile % (Wd/QT)) * QT;
    int t = threadIdx.x;
    int lane = t & 31, warp = t >> 5;
    int g = lane >> 2, t4 = lane & 3;

    if (t < W2Sd) sbr[t] = brel[h*W2Sd + t];

    // ---- rel MMA prologue: sRel[16q][225o] = Qtile x Wrel[h]^T ----
    {
        unsigned aq[4][4];
        int q0 = g, q1 = g + 8;
        int tk0 = b*HW + (ty0 + (q0 >> 2))*Wd + tx0 + (q0 & 3);
        int tk1 = b*HW + (ty0 + (q1 >> 2))*Wd + tx0 + (q1 & 3);
        const float* Q0 = g_Q + (size_t)tk0*Cd + h*HDd;
        const float* Q1 = g_Q + (size_t)tk1*Cd + h*HDd;
        #pragma unroll
        for (int ks = 0; ks < 4; ks++) {
            aq[ks][0] = f2tf32(Q0[ks*8 + t4]);
            aq[ks][1] = f2tf32(Q1[ks*8 + t4]);
            aq[ks][2] = f2tf32(Q0[ks*8 + t4 + 4]);
            aq[ks][3] = f2tf32(Q1[ks*8 + t4 + 4]);
        }
        const float* Wh = Wrel + (size_t)h*W2Sd*HDd;
        for (int nt = warp; nt < 29; nt += 8) {
            int n0 = nt*8;
            int o = n0 + g;
            float c0 = 0.f, c1 = 0.f, c2 = 0.f, c3 = 0.f;
            #pragma unroll
            for (int ks = 0; ks < 4; ks++) {
                float w0 = 0.f, w1 = 0.f;
                if (o < W2Sd) {
                    w0 = Wh[o*HDd + ks*8 + t4];
                    w1 = Wh[o*HDd + ks*8 + t4 + 4];
                }
                mma_tf32(c0, c1, c2, c3,
                         aq[ks][0], aq[ks][1], aq[ks][2], aq[ks][3],
                         f2tf32(w0), f2tf32(w1));
            }
            sRel[g*RELP + n0 + 2*t4]         = c0;
            sRel[g*RELP + n0 + 2*t4 + 1]     = c1;
            sRel[(g+8)*RELP + n0 + 2*t4]     = c2;
            sRel[(g+8)*RELP + n0 + 2*t4 + 1] = c3;
        }
    }

    // ---- K window load: bf16x2 channel pairs, zero-padded OOB ----
    int wy0 = ty0 - MDd, wx0 = tx0 - MDd;
    for (int i = t; i < EXT2*16; i += 256) {
        int pos = i >> 4, c2 = i & 15;
        int wy = pos / EXT, wx = pos - (pos/EXT)*EXT;
        int ky = wy0 + wy, kx = wx0 + wx;
        float2 v = make_float2(0.f, 0.f);
        if (ky >= 0 && ky < Hh && kx >= 0 && kx < Wd)
            v = *(const float2*)(g_K + (size_t)(b*HW + ky*Wd + kx)*Cd + h*HDd + c2*2);
        sKh[c2*KPAD + pos] = __float22bfloat162_rn(v);
    }
    __syncthreads();

    // ---- score loop ----
    int q  = t >> 4;
    int lo = t & 15;
    int qy = q >> 2, qx = q & 3;
    int ty = ty0 + qy, tx = tx0 + qx;
    int tok = b*HW + ty*Wd + tx;
    float qreg[32];
    {
        const float* qp = g_Q + (size_t)tok*Cd + h*HDd;
        #pragma unroll
        for (int c = 0; c < 32; c++) qreg[c] = qp[c];
    }

    const float scale = 0.17677669529663687f;
    for (int o = lo; o < W2Sd; o += 16) {
        int oy = o / WSd, ox = o - (o/WSd)*WSd;
        int ky = ty + oy - MDd, kx = tx + ox - MDd;
        float s = NEGINF;
        if (ky >= 0 && ky < Hh && kx >= 0 && kx < Wd) {
            int pos = (qy + oy)*EXT + (qx + ox);
            float d = 0.f;
            #pragma unroll
            for (int c2 = 0; c2 < 16; c2++) {
                float2 kv = __bfloat1622float2(sKh[c2*KPAD + pos]);
                d += qreg[2*c2]*kv.x + qreg[2*c2+1]*kv.y;
            }
            s = d*scale + sRel[q*RELP + o] + sbr[o];
        }
        sS[q*SPAD + o] = s;
    }
    __syncthreads();

    // ---- softmax ----
    {
        float mx = NEGINF;
        for (int o = lo; o < W2Sd; o += 16)
            mx = fmaxf(mx, sS[q*SPAD + o]);
        #pragma unroll
        for (int d = 8; d > 0; d >>= 1)
            mx = fmaxf(mx, __shfl_xor_sync(0xffffffffu, mx, d));
        float sum = 0.f;
        for (int o = lo; o < W2Sd; o += 16) {
            float s = sS[q*SPAD + o];
            float e = (s > -1e37f) ? __expf(s - mx) : 0.f;
            sS[q*SPAD + o] = e;
            sum += e;
        }
        #pragma unroll
        for (int d = 8; d > 0; d >>= 1)
            sum += __shfl_xor_sync(0xffffffffu, sum, d);
        if (lo == 0) sInv[q] = 1.f / sum;
    }
    __syncthreads();

    // ---- V window (reuse sKh, bf16x2) ----
    for (int i = t; i < EXT2*16; i += 256) {
        int pos = i >> 4, c2 = i & 15;
        int wy = pos / EXT, wx = pos - (pos/EXT)*EXT;
        int ky = wy0 + wy, kx = wx0 + wx;
        float2 v = make_float2(0.f, 0.f);
        if (ky >= 0 && ky < Hh && kx >= 0 && kx < Wd)
            v = *(const float2*)(g_V + (size_t)(b*HW + ky*Wd + kx)*Cd + h*HDd + c2*2);
        sKh[c2*KPAD + pos] = __float22bfloat162_rn(v);
    }
    __syncthreads();

    // ---- weighted V sum: thread = (query, channel pair) ----
    {
        int c2 = t & 15;
        float ax = 0.f, ay = 0.f;
        #pragma unroll
        for (int oy = 0; oy < WSd; oy++) {
            int pos0 = (qy + oy)*EXT + qx;
            int srow = q*SPAD + oy*WSd;
            #pragma unroll
            for (int ox = 0; ox < WSd; ox++) {
                float p = sS[srow + ox];
                float2 v = __bfloat1622float2(sKh[c2*KPAD + pos0 + ox]);
                ax += p*v.x;
                ay += p*v.y;
            }
        }
        float inv = sInv[q];
        float2 o2 = make_float2(ax*inv, ay*inv);
        *(float2*)(g_att + (size_t)tok*Cd + h*HDd + c2*2) = o2;
    }
}

// ---------------- GroupNorm stats per (b, group) ----------------
__global__ void gn_stats_kernel() {
    int bg = blockIdx.x;
    int b = bg / GNg, g = bg % GNg;
    int tid = threadIdx.x;
    float sm = 0.f, sq = 0.f;
    for (int i = tid; i < HW*32; i += 256) {
        int ch  = g*32 + (i & 31);
        int pos = i >> 5;
        float v = g_h1[(size_t)(b*HW + pos)*HIDd + ch];
        sm += v; sq += v*v;
    }
    #pragma unroll
    for (int d = 16; d > 0; d >>= 1) {
        sm += __shfl_xor_sync(0xffffffffu, sm, d);
        sq += __shfl_xor_sync(0xffffffffu, sq, d);
    }
    __shared__ float s1[8], s2[8];
    int warp = tid >> 5, lane = tid & 31;
    if (lane == 0) { s1[warp] = sm; s2[warp] = sq; }
    __syncthreads();
    if (tid == 0) {
        float ss = 0.f, qq = 0.f;
        #pragma unroll
        for (int i = 0; i < 8; i++) { ss += s1[i]; qq += s2[i]; }
        float cnt = (float)(HW*32);
        float mu  = ss / cnt;
        float var = qq / cnt - mu*mu;
        g_gnm[bg*2]   = mu;
        g_gnm[bg*2+1] = rsqrtf(var + EPSf);
    }
}

// ---------------- fused GN + GELU + 5x5 depthwise conv ----------------
__global__ void dwconv_fused_kernel(const float* __restrict__ gg,
                                    const float* __restrict__ gb,
                                    const float* __restrict__ Wdw) {
    __shared__ float sT[144][68];

    int tileid = blockIdx.x;
    int cg = blockIdx.y, b = blockIdx.z;
    int ty0 = (tileid / 5) * 8, tx0 = (tileid % 5) * 8;
    int tid = threadIdx.x;
    int ch  = tid & 63;
    int chg = cg*64 + ch;

    float gamma = gg[chg], beta = gb[chg];
    int grp = chg >> 5;
    float mu = g_gnm[(b*GNg + grp)*2];
    float rs = g_gnm[(b*GNg + grp)*2 + 1];

    float wreg[25];
    #pragma unroll
    for (int i = 0; i < 25; i++) wreg[i] = Wdw[chg*25 + i];

    for (int i = tid; i < 144*64; i += 256) {
        int pos = i >> 6;
        int wy = pos / 12, wx = pos - (pos/12)*12;
        int y = ty0 + wy - 2, x = tx0 + wx - 2;
        float v = 0.f;
        if (y >= 0 && y < Hh && x >= 0 && x < Wd) {
            float hv = g_h1[(size_t)(b*HW + y*Wd + x)*HIDd + chg];
            hv = (hv - mu) * rs * gamma + beta;
            v = 0.5f * hv * (1.f + erff(hv * 0.70710678118654752f));
        }
        sT[pos][ch] = v;
    }
    __syncthreads();

    int pg = tid >> 6;
    #pragma unroll
    for (int p = 0; p < 16; p++) {
        int po = pg*16 + p;
        int y = po >> 3, x = po & 7;
        float acc = 0.f;
        #pragma unroll
        for (int dy = 0; dy < 5; dy++)
            #pragma unroll
            for (int dx = 0; dx < 5; dx++)
                acc += wreg[dy*5+dx] * sT[(y+dy)*12 + (x+dx)][ch];
        g_cv[(size_t)(b*HW + (ty0+y)*Wd + (tx0+x))*HIDd + chg] = acc;
    }
}

// ---------------- launch ----------------
extern "C" void kernel_launch(void* const* d_in, const int* in_sizes, int n_in,
                              void* d_out, int out_size) {
    const float* img   = (const float*)d_in[0];
    const float* imw   = (const float*)d_in[1];
    const float* msk   = (const float*)d_in[2];
    const float* ln1g  = (const float*)d_in[3];
    const float* ln1b  = (const float*)d_in[4];
    const float* ln2g  = (const float*)d_in[5];
    const float* ln2b  = (const float*)d_in[6];
    const float* Wq    = (const float*)d_in[7];
    const float* bq    = (const float*)d_in[8];
    const float* Wk    = (const float*)d_in[9];
    const float* bk    = (const float*)d_in[10];
    const float* Wv    = (const float*)d_in[11];
    const float* bv    = (const float*)d_in[12];
    const float* Wrel  = (const float*)d_in[13];
    const float* brel  = (const float*)d_in[14];
    const float* Wproj = (const float*)d_in[15];
    const float* bproj = (const float*)d_in[16];
    const float* W1    = (const float*)d_in[17];
    const float* bW1   = (const float*)d_in[18];
    const float* gng   = (const float*)d_in[19];
    const float* gnb   = (const float*)d_in[20];
    const float* Wdw   = (const float*)d_in[21];
    const float* W2    = (const float*)d_in[22];
    const float* bW2   = (const float*)d_in[23];
    float* out = (float*)d_out;

    float *qln, *kln, *vln, *Q, *K, *V, *att, *x1, *ln2, *h1, *cv;
    cudaGetSymbolAddress((void**)&qln, g_qln);
    cudaGetSymbolAddress((void**)&kln, g_kln);
    cudaGetSymbolAddress((void**)&vln, g_vln);
    cudaGetSymbolAddress((void**)&Q,   g_Q);
    cudaGetSymbolAddress((void**)&K,   g_K);
    cudaGetSymbolAddress((void**)&V,   g_V);
    cudaGetSymbolAddress((void**)&att, g_att);
    cudaGetSymbolAddress((void**)&x1,  g_x1);
    cudaGetSymbolAddress((void**)&ln2, g_ln2);
    cudaGetSymbolAddress((void**)&h1,  g_h1);
    cudaGetSymbolAddress((void**)&cv,  g_cv);

    int smem128 = (2*128*KP + 2*BN*KP) * sizeof(float);
    cudaFuncSetAttribute(mma_gemm_kernel<128>,
                         cudaFuncAttributeMaxDynamicSharedMemorySize, smem128);
    cudaFuncSetAttribute(mma_qkv_kernel,
                         cudaFuncAttributeMaxDynamicSharedMemorySize, smem128);

    // zero split-K accumulation targets (capturable async memsets)
    cudaMemsetAsync(x1, 0, (size_t)TOK*Cd*sizeof(float));
    cudaMemsetAsync(out, 0, (size_t)TOK*Cd*sizeof(float));

    // 1. LayerNorms
    ln3_kernel<<<TOK, 256>>>(img, imw, msk, ln1g, ln1b);

    // 2. QKV projections
    QKVArgs qa;
    qa.A[0] = qln; qa.A[1] = kln; qa.A[2] = vln;
    qa.W[0] = Wq;  qa.W[1] = Wk;  qa.W[2] = Wv;
    qa.bias[0] = bq; qa.bias[1] = bk; qa.bias[2] = bv;
    qa.C[0] = Q; qa.C[1] = K; qa.C[2] = V;
    mma_qkv_kernel<<<dim3(Cd/BN, TOK/128, 3), 256, smem128>>>(qa);

    // 3. tiled windowed attention
    int attn_smem = (16*KPAD + 16*SPAD + 16*RELP + 16 + 228) * sizeof(float);
    cudaFuncSetAttribute(attn_tile_kernel,
                         cudaFuncAttributeMaxDynamicSharedMemorySize, attn_smem);
    attn_tile_kernel<<<dim3((Hh/QT)*(Wd/QT), NHd, Bz), 256, attn_smem>>>(Wrel, brel);

    // 4. output projection + fused residual -> x1  (split-K=2, atomic)
    mma_gemm_kernel<128><<<dim3(Cd/BN, TOK/128, 2), 256, smem128>>>(att, Wproj, bproj, x1,
                                                                    Cd, Cd, 1, img);

    // 5. MLP branch
    ln_tok_kernel<<<TOK, 256>>>(ln2g, ln2b);
    mma_gemm_kernel<128><<<dim3(HIDd/BN, TOK/128, 1), 256, smem128>>>(ln2, W1, bW1, h1,
                                                                      HIDd, Cd, 0, nullptr);
    gn_stats_kernel<<<Bz*GNg, 256>>>();
    dwconv_fused_kernel<<<dim3(25, HIDd/64, Bz), 256>>>(gng, gnb, Wdw);

    // 6. W2 + fused final residual + transpose to BCHW  (split-K=2, atomic)
    mma_gemm_kernel<128><<<dim3(Cd/BN, TOK/128, 2), 256, smem128>>>(cv, W2, bW2, out,
                                                                    Cd, HIDd, 2, x1);
}

// round 14
// speedup vs baseline: 1.0017x; 1.0017x over previous
#include <cuda_runtime.h>
#include <cuda_bf16.h>
#include <math.h>

#define Bz   2
#define Cd   256
#define Hh   40
#define Wd   40
#define HW   1600
#define TOK  3200
#define NHd  8
#define HDd  32
#define WSd  15
#define W2Sd 225
#define MDd  7
#define HIDd 1024
#define GNg  32
#define EPSf 1e-5f
#define NEGINF -1e38f

// attention tiling
#define QT    4
#define EXT   18
#define EXT2  (EXT*EXT)    // 324
#define EXTP  336          // padded to 21 k16 steps
#define PKW   20           // K-phase row stride (u32 words), [pos][ch-pairs]
#define PVW   172          // P/V row stride (u32 words), rows of 344 bf16
#define SSP   340          // score row stride (fp32)
#define RELP  236

// GEMM tiling
#define BN 64
#define BK 32
#define KP 36

// ---------------- scratch ----------------
__device__ float g_qln[TOK*Cd];
__device__ float g_kln[TOK*Cd];
__device__ float g_vln[TOK*Cd];
__device__ float g_Q[TOK*Cd];
__device__ float g_K[TOK*Cd];
__device__ float g_V[TOK*Cd];
__device__ float g_att[TOK*Cd];
__device__ float g_x1[TOK*Cd];
__device__ float g_ln2[TOK*Cd];
__device__ float g_h1[TOK*HIDd];
__device__ float g_cv[TOK*HIDd];
__device__ float g_gnm[Bz*GNg*2];

// ---------------- block mean/var helper (256 threads) ----------------
__device__ __forceinline__ void block_meanvar(float v, float* sbuf,
                                              float& mu, float& rstd) {
    float s = v, q = v*v;
    #pragma unroll
    for (int d = 16; d > 0; d >>= 1) {
        s += __shfl_xor_sync(0xffffffffu, s, d);
        q += __shfl_xor_sync(0xffffffffu, q, d);
    }
    int warp = threadIdx.x >> 5, lane = threadIdx.x & 31;
    if (lane == 0) { sbuf[warp] = s; sbuf[8 + warp] = q; }
    __syncthreads();
    if (warp == 0) {
        float ss = (lane < 8) ? sbuf[lane] : 0.f;
        float qq = (lane < 8) ? sbuf[8 + lane] : 0.f;
        #pragma unroll
        for (int d = 4; d > 0; d >>= 1) {
            ss += __shfl_xor_sync(0xffffffffu, ss, d);
            qq += __shfl_xor_sync(0xffffffffu, qq, d);
        }
        if (lane == 0) {
            float m = ss * (1.0f/Cd);
            float var = qq * (1.0f/Cd) - m*m;
            sbuf[16] = m;
            sbuf[17] = rsqrtf(var + EPSf);
        }
    }
    __syncthreads();
    mu = sbuf[16]; rstd = sbuf[17];
}

// ---------------- fused LN of img / img_warp / img_warp+mask ----------------
__global__ void ln3_kernel(const float* __restrict__ img,
                           const float* __restrict__ imw,
                           const float* __restrict__ msk,
                           const float* __restrict__ g1,
                           const float* __restrict__ b1) {
    int tok = blockIdx.x;
    int c   = threadIdx.x;
    int b   = tok / HW, pos = tok % HW;
    int off = (b*Cd + c)*HW + pos;

    float x0 = img[off];
    float x1 = imw[off];
    float x2 = x1 + msk[off];
    float gg = g1[c], bb = b1[c];

    __shared__ float sbuf[18];
    float mu, rs;

    block_meanvar(x0, sbuf, mu, rs);
    g_qln[tok*Cd + c] = (x0 - mu) * rs * gg + bb;
    __syncthreads();
    block_meanvar(x1, sbuf, mu, rs);
    g_kln[tok*Cd + c] = (x1 - mu) * rs * gg + bb;
    __syncthreads();
    block_meanvar(x2, sbuf, mu, rs);
    g_vln[tok*Cd + c] = (x2 - mu) * rs * gg + bb;
}

__global__ void ln_tok_kernel(const float* __restrict__ g1,
                              const float* __restrict__ b1) {
    int tok = blockIdx.x;
    int c   = threadIdx.x;
    float v = g_x1[tok*Cd + c];
    __shared__ float sbuf[18];
    float mu, rs;
    block_meanvar(v, sbuf, mu, rs);
    g_ln2[tok*Cd + c] = (v - mu) * rs * g1[c] + b1[c];
}

// ---------------- MMA helpers ----------------
__device__ __forceinline__ unsigned f2tf32(float x) {
    unsigned r;
    asm("cvt.rna.tf32.f32 %0, %1;" : "=r"(r) : "f"(x));
    return r;
}
__device__ __forceinline__ void mma_tf32(float& c0, float& c1, float& c2, float& c3,
                                         unsigned a0, unsigned a1, unsigned a2, unsigned a3,
                                         unsigned b0, unsigned b1) {
    asm volatile(
        "mma.sync.aligned.m16n8k8.row.col.f32.tf32.tf32.f32 "
        "{%0,%1,%2,%3}, {%4,%5,%6,%7}, {%8,%9}, {%0,%1,%2,%3};"
        : "+f"(c0), "+f"(c1), "+f"(c2), "+f"(c3)
        : "r"(a0), "r"(a1), "r"(a2), "r"(a3), "r"(b0), "r"(b1));
}
__device__ __forceinline__ void mma_bf16(float& c0, float& c1, float& c2, float& c3,
                                         unsigned a0, unsigned a1, unsigned a2, unsigned a3,
                                         unsigned b0, unsigned b1) {
    asm volatile(
        "mma.sync.aligned.m16n8k16.row.col.f32.bf16.bf16.f32 "
        "{%0,%1,%2,%3}, {%4,%5,%6,%7}, {%8,%9}, {%0,%1,%2,%3};"
        : "+f"(c0), "+f"(c1), "+f"(c2), "+f"(c3)
        : "r"(a0), "r"(a1), "r"(a2), "r"(a3), "r"(b0), "r"(b1));
}
__device__ __forceinline__ void cp_async16(unsigned dst, const void* src) {
    asm volatile("cp.async.cg.shared.global [%0], [%1], 16;\n"
                 :: "r"(dst), "l"(src));
}
__device__ __forceinline__ void cp_commit() {
    asm volatile("cp.async.commit_group;\n");
}

// ---------------- tf32 GEMM, cp.async double buffered (round-10) ----------
template<int BMT>
__device__ __forceinline__ void mma_body(const float* __restrict__ A, int lda,
                                         const float* __restrict__ Wt,
                                         const float* __restrict__ bias,
                                         float* __restrict__ C,
                                         int N, int K, int m0, int n0,
                                         int mode, const float* __restrict__ res) {
    constexpr int MT = BMT / 64;
    extern __shared__ float smem[];
    float* As = smem;
    float* Ws = smem + 2*BMT*KP;

    int tid  = threadIdx.x;
    int lane = tid & 31, warp = tid >> 5;
    int wm = (warp >> 1) * (16*MT), wn = (warp & 1) * 32;
    int g = lane >> 2, t4 = lane & 3;

    float acc[MT][4][4] = {};
    int steps = K / BK;

    unsigned sA = (unsigned)__cvta_generic_to_shared(As);
    unsigned sW = (unsigned)__cvta_generic_to_shared(Ws);

    auto load_stage = [&](int kc, int s) {
        int k0 = kc * BK;
        #pragma unroll
        for (int it = 0; it < BMT/32; it++) {
            int idx = tid + it*256;
            int row = idx >> 3, ch = (idx & 7) * 4;
            cp_async16(sA + (unsigned)(((s*BMT + row)*KP + ch) * 4),
                       &A[(size_t)(m0+row)*lda + k0 + ch]);
        }
        #pragma unroll
        for (int it = 0; it < 2; it++) {
            int idx = tid + it*256;
            int row = idx >> 3, ch = (idx & 7) * 4;
            cp_async16(sW + (unsigned)(((s*BN + row)*KP + ch) * 4),
                       &Wt[(size_t)(n0+row)*K + k0 + ch]);
        }
        cp_commit();
    };

    load_stage(0, 0);

    for (int kc = 0; kc < steps; kc++) {
        int s = kc & 1;
        if (kc + 1 < steps) {
            load_stage(kc + 1, (kc + 1) & 1);
            asm volatile("cp.async.wait_group 1;\n");
        } else {
            asm volatile("cp.async.wait_group 0;\n");
        }
        __syncthreads();

        float* Ab = As + s*BMT*KP;
        float* Wb = Ws + s*BN*KP;
        #pragma unroll
        for (int ks = 0; ks < BK; ks += 8) {
            unsigned a[MT][4], bf[4][2];
            #pragma unroll
            for (int mt = 0; mt < MT; mt++) {
                int rb = wm + mt*16;
                a[mt][0] = f2tf32(Ab[(rb + g    )*KP + ks + t4    ]);
                a[mt][1] = f2tf32(Ab[(rb + g + 8)*KP + ks + t4    ]);
                a[mt][2] = f2tf32(Ab[(rb + g    )*KP + ks + t4 + 4]);
                a[mt][3] = f2tf32(Ab[(rb + g + 8)*KP + ks + t4 + 4]);
            }
            #pragma unroll
            for (int nt = 0; nt < 4; nt++) {
                int nb = wn + nt*8 + g;
                bf[nt][0] = f2tf32(Wb[nb*KP + ks + t4    ]);
                bf[nt][1] = f2tf32(Wb[nb*KP + ks + t4 + 4]);
            }
            #pragma unroll
            for (int mt = 0; mt < MT; mt++)
                #pragma unroll
                for (int nt = 0; nt < 4; nt++)
                    mma_tf32(acc[mt][nt][0], acc[mt][nt][1],
                             acc[mt][nt][2], acc[mt][nt][3],
                             a[mt][0], a[mt][1], a[mt][2], a[mt][3],
                             bf[nt][0], bf[nt][1]);
        }
        __syncthreads();
    }

    #pragma unroll
    for (int mt = 0; mt < MT; mt++) {
        #pragma unroll
        for (int nt = 0; nt < 4; nt++) {
            #pragma unroll
            for (int i = 0; i < 4; i++) {
                int mrow = m0 + wm + mt*16 + g + ((i >= 2) ? 8 : 0);
                int ncol = n0 + wn + nt*8 + 2*t4 + (i & 1);
                float v = acc[mt][nt][i] + bias[ncol];
                if (mode == 0) {
                    C[(size_t)mrow*N + ncol] = v;
                } else if (mode == 1) {
                    int b = mrow / HW, pos = mrow % HW;
                    C[(size_t)mrow*N + ncol] =
                        v + res[(size_t)(b*Cd + ncol)*HW + pos];
                } else {
                    int b = mrow / HW, pos = mrow % HW;
                    C[(size_t)(b*Cd + ncol)*HW + pos] =
                        v + res[(size_t)mrow*N + ncol];
                }
            }
        }
    }
}

template<int BMT>
__global__ void mma_gemm_kernel(const float* __restrict__ A,
                                const float* __restrict__ Wt,
                                const float* __restrict__ bias,
                                float* __restrict__ C,
                                int N, int K, int mode,
                                const float* __restrict__ res) {
    mma_body<BMT>(A, K, Wt, bias, C, N, K, blockIdx.y*BMT, blockIdx.x*BN, mode, res);
}

struct QKVArgs {
    const float* A[3];
    const float* W[3];
    const float* bias[3];
    float* C[3];
};
__global__ void mma_qkv_kernel(QKVArgs args) {
    int z = blockIdx.z;
    mma_body<128>(args.A[z], Cd, args.W[z], args.bias[z], args.C[z],
                  Cd, Cd, blockIdx.y*128, blockIdx.x*BN, 0, nullptr);
}

// ---------------- tensor-core local attention v2 (bf16 fragments) ----------
__global__ void attn_tile_kernel(const float* __restrict__ Wrel,
                                 const float* __restrict__ brel) {
    extern __shared__ float smem[];
    unsigned* sQ  = (unsigned*)smem;            // [16 q][PKW]   bf16x2 (scaled)
    unsigned* sKV = sQ + 16*PKW;                // [336][PKW] K  / [32][PVW] V
    float*    sS  = (float*)(sKV + EXTP*PKW);   // [16][SSP]
    unsigned* sP  = (unsigned*)(sS + 16*SSP);   // [16 q][PVW]   bf16 probs
    float*   sRed = (float*)(sP + 16*PVW);      // [512]
    float*   sRel = sRed + 512;                 // [16][RELP]
    float*   sInv = sRel + 16*RELP;             // [16]
    float*   sbr  = sInv + 16;                  // [228]

    int tile = blockIdx.x;
    int h = blockIdx.y, b = blockIdx.z;
    int ty0 = (tile / (Wd/QT)) * QT;
    int tx0 = (tile % (Wd/QT)) * QT;
    int t = threadIdx.x;
    int lane = t & 31, warp = t >> 5;
    int g = lane >> 2, t4 = lane & 3;

    const float scale = 0.17677669529663687f;
    int wy0 = ty0 - MDd, wx0 = tx0 - MDd;

    if (t < W2Sd) sbr[t] = brel[h*W2Sd + t];

    // ---- rel MMA prologue: sRel[16q][225o] = Qtile x Wrel[h]^T (tf32) ----
    {
        unsigned aq[4][4];
        int q0 = g, q1 = g + 8;
        int tk0 = b*HW + (ty0 + (q0 >> 2))*Wd + tx0 + (q0 & 3);
        int tk1 = b*HW + (ty0 + (q1 >> 2))*Wd + tx0 + (q1 & 3);
        const float* Q0 = g_Q + (size_t)tk0*Cd + h*HDd;
        const float* Q1 = g_Q + (size_t)tk1*Cd + h*HDd;
        #pragma unroll
        for (int ks = 0; ks < 4; ks++) {
            aq[ks][0] = f2tf32(Q0[ks*8 + t4]);
            aq[ks][1] = f2tf32(Q1[ks*8 + t4]);
            aq[ks][2] = f2tf32(Q0[ks*8 + t4 + 4]);
            aq[ks][3] = f2tf32(Q1[ks*8 + t4 + 4]);
        }
        const float* Wh = Wrel + (size_t)h*W2Sd*HDd;
        for (int nt = warp; nt < 29; nt += 8) {
            int n0 = nt*8;
            int o = n0 + g;
            float c0 = 0.f, c1 = 0.f, c2 = 0.f, c3 = 0.f;
            #pragma unroll
            for (int ks = 0; ks < 4; ks++) {
                float w0 = 0.f, w1 = 0.f;
                if (o < W2Sd) {
                    w0 = Wh[o*HDd + ks*8 + t4];
                    w1 = Wh[o*HDd + ks*8 + t4 + 4];
                }
                mma_tf32(c0, c1, c2, c3,
                         aq[ks][0], aq[ks][1], aq[ks][2], aq[ks][3],
                         f2tf32(w0), f2tf32(w1));
            }
            sRel[g*RELP + n0 + 2*t4]         = c0;
            sRel[g*RELP + n0 + 2*t4 + 1]     = c1;
            sRel[(g+8)*RELP + n0 + 2*t4]     = c2;
            sRel[(g+8)*RELP + n0 + 2*t4 + 1] = c3;
        }
    }

    // ---- pack scaled Q as bf16x2 ----
    {
        int q = t >> 4, c2 = t & 15;
        int qy = q >> 2, qx = q & 3;
        int tokq = b*HW + (ty0+qy)*Wd + tx0+qx;
        float2 v = *(const float2*)(g_Q + (size_t)tokq*Cd + h*HDd + c2*2);
        v.x *= scale; v.y *= scale;
        ((__nv_bfloat162*)sQ)[q*PKW + c2] = __float22bfloat162_rn(v);
    }

    // ---- K load: pos-major bf16x2, zero-padded (incl. pos >= EXT2) ----
    for (int i = t; i < EXTP*16; i += 256) {
        int pos = i >> 4, c2 = i & 15;
        float2 v = make_float2(0.f, 0.f);
        if (pos < EXT2) {
            int wy = pos / EXT, wx = pos - (pos/EXT)*EXT;
            int ky = wy0 + wy, kx = wx0 + wx;
            if (ky >= 0 && ky < Hh && kx >= 0 && kx < Wd)
                v = *(const float2*)(g_K + (size_t)(b*HW + ky*Wd + kx)*Cd + h*HDd + c2*2);
        }
        ((__nv_bfloat162*)sKV)[pos*PKW + c2] = __float22bfloat162_rn(v);
    }
    __syncthreads();

    // ---- score MMA: sS[16][336] = Qs x Kext^T (bf16) ----
    {
        unsigned a[2][4];
        #pragma unroll
        for (int ks = 0; ks < 2; ks++) {
            a[ks][0] = sQ[g*PKW + ks*8 + t4];
            a[ks][1] = sQ[(g+8)*PKW + ks*8 + t4];
            a[ks][2] = sQ[g*PKW + ks*8 + t4 + 4];
            a[ks][3] = sQ[(g+8)*PKW + ks*8 + t4 + 4];
        }
        for (int nt = warp; nt < EXTP/8; nt += 8) {
            int n0 = nt*8;
            float c0 = 0.f, c1 = 0.f, c2v = 0.f, c3 = 0.f;
            #pragma unroll
            for (int ks = 0; ks < 2; ks++) {
                unsigned b0 = sKV[(n0+g)*PKW + ks*8 + t4];
                unsigned b1 = sKV[(n0+g)*PKW + ks*8 + t4 + 4];
                mma_bf16(c0, c1, c2v, c3,
                         a[ks][0], a[ks][1], a[ks][2], a[ks][3], b0, b1);
            }
            sS[g*SSP + n0 + 2*t4]         = c0;
            sS[g*SSP + n0 + 2*t4 + 1]     = c1;
            sS[(g+8)*SSP + n0 + 2*t4]     = c2v;
            sS[(g+8)*SSP + n0 + 2*t4 + 1] = c3;
        }
    }
    __syncthreads();

    // ---- zero P and V regions ----
    for (int i = t; i < 16*PVW; i += 256) sP[i] = 0;
    for (int i = t; i < 32*PVW; i += 256) sKV[i] = 0;
    __syncthreads();

    // ---- V load: channel-major bf16 [32 ch][344 pos-slots] ----
    {
        __nv_bfloat16* vb = (__nv_bfloat16*)sKV;
        for (int i = t; i < EXT2*16; i += 256) {
            int pos = i >> 4, c2 = i & 15;
            int wy = pos / EXT, wx = pos - (pos/EXT)*EXT;
            int ky = wy0 + wy, kx = wx0 + wx;
            if (ky >= 0 && ky < Hh && kx >= 0 && kx < Wd) {
                float2 v = *(const float2*)(g_V + (size_t)(b*HW + ky*Wd + kx)*Cd + h*HDd + c2*2);
                vb[(2*c2    )*(2*PVW) + pos] = __float2bfloat16(v.x);
                vb[(2*c2 + 1)*(2*PVW) + pos] = __float2bfloat16(v.y);
            }
        }
    }

    // ---- masked softmax: 16 lanes per query; scatter bf16 probs into sP ----
    {
        int q = t >> 4, lo = t & 15;
        int qy = q >> 2, qx = q & 3;
        float mx = NEGINF;
        for (int o = lo; o < W2Sd; o += 16) {
            int oy = o / WSd, ox = o - (o/WSd)*WSd;
            int ky = ty0 + qy + oy - MDd, kx = tx0 + qx + ox - MDd;
            if (ky >= 0 && ky < Hh && kx >= 0 && kx < Wd) {
                int pos = (qy + oy)*EXT + (qx + ox);
                float s = sS[q*SSP + pos] + sRel[q*RELP + o] + sbr[o];
                mx = fmaxf(mx, s);
            }
        }
        #pragma unroll
        for (int d = 8; d > 0; d >>= 1)
            mx = fmaxf(mx, __shfl_xor_sync(0xffffffffu, mx, d));
        float sum = 0.f;
        __nv_bfloat16* pb = (__nv_bfloat16*)sP;
        for (int o = lo; o < W2Sd; o += 16) {
            int oy = o / WSd, ox = o - (o/WSd)*WSd;
            int ky = ty0 + qy + oy - MDd, kx = tx0 + qx + ox - MDd;
            if (ky >= 0 && ky < Hh && kx >= 0 && kx < Wd) {
                int pos = (qy + oy)*EXT + (qx + ox);
                float s = sS[q*SSP + pos] + sRel[q*RELP + o] + sbr[o];
                float e = __expf(s - mx);
                pb[q*(2*PVW) + pos] = __float2bfloat16(e);
                sum += e;
            }
        }
        #pragma unroll
        for (int d = 8; d > 0; d >>= 1)
            sum += __shfl_xor_sync(0xffffffffu, sum, d);
        if (lo == 0) sInv[q] = 1.f / sum;
    }
    __syncthreads();

    // ---- PV MMA: O[16][32] = P x Vext ; warp = (khalf, ntile) ----
    {
        int khalf = warp >> 2, ntile = warp & 3;
        int n0 = ntile*8;
        int ks0 = khalf ? 11 : 0, ks1 = khalf ? 21 : 11;
        float c0 = 0.f, c1 = 0.f, c2v = 0.f, c3 = 0.f;
        for (int ks = ks0; ks < ks1; ks++) {
            int kw = ks*8;
            unsigned a0 = sP[g*PVW + kw + t4];
            unsigned a1 = sP[(g+8)*PVW + kw + t4];
            unsigned a2 = sP[g*PVW + kw + t4 + 4];
            unsigned a3 = sP[(g+8)*PVW + kw + t4 + 4];
            unsigned b0 = sKV[(n0+g)*PVW + kw + t4];
            unsigned b1 = sKV[(n0+g)*PVW + kw + t4 + 4];
            mma_bf16(c0, c1, c2v, c3, a0, a1, a2, a3, b0, b1);
        }
        if (khalf == 1) {
            sRed[ntile*128 + g*8 + 2*t4]           = c0;
            sRed[ntile*128 + g*8 + 2*t4 + 1]       = c1;
            sRed[ntile*128 + (g+8)*8 + 2*t4]       = c2v;
            sRed[ntile*128 + (g+8)*8 + 2*t4 + 1]   = c3;
        }
        __syncthreads();
        if (khalf == 0) {
            c0  += sRed[ntile*128 + g*8 + 2*t4];
            c1  += sRed[ntile*128 + g*8 + 2*t4 + 1];
            c2v += sRed[ntile*128 + (g+8)*8 + 2*t4];
            c3  += sRed[ntile*128 + (g+8)*8 + 2*t4 + 1];
            int q0 = g, q1 = g + 8;
            int tok0 = b*HW + (ty0 + (q0 >> 2))*Wd + tx0 + (q0 & 3);
            int tok1 = b*HW + (ty0 + (q1 >> 2))*Wd + tx0 + (q1 & 3);
            float i0 = sInv[q0], i1 = sInv[q1];
            float* o0 = g_att + (size_t)tok0*Cd + h*HDd + n0 + 2*t4;
            float* o1 = g_att + (size_t)tok1*Cd + h*HDd + n0 + 2*t4;
            o0[0] = c0  * i0; o0[1] = c1 * i0;
            o1[0] = c2v * i1; o1[1] = c3 * i1;
        }
    }
}

// ---------------- GroupNorm stats per (b, group) ----------------
__global__ void gn_stats_kernel() {
    int bg = blockIdx.x;
    int b = bg / GNg, g = bg % GNg;
    int tid = threadIdx.x;
    float sm = 0.f, sq = 0.f;
    for (int i = tid; i < HW*32; i += 256) {
        int ch  = g*32 + (i & 31);
        int pos = i >> 5;
        float v = g_h1[(size_t)(b*HW + pos)*HIDd + ch];
        sm += v; sq += v*v;
    }
    #pragma unroll
    for (int d = 16; d > 0; d >>= 1) {
        sm += __shfl_xor_sync(0xffffffffu, sm, d);
        sq += __shfl_xor_sync(0xffffffffu, sq, d);
    }
    __shared__ float s1[8], s2[8];
    int warp = tid >> 5, lane = tid & 31;
    if (lane == 0) { s1[warp] = sm; s2[warp] = sq; }
    __syncthreads();
    if (tid == 0) {
        float ss = 0.f, qq = 0.f;
        #pragma unroll
        for (int i = 0; i < 8; i++) { ss += s1[i]; qq += s2[i]; }
        float cnt = (float)(HW*32);
        float mu  = ss / cnt;
        float var = qq / cnt - mu*mu;
        g_gnm[bg*2]   = mu;
        g_gnm[bg*2+1] = rsqrtf(var + EPSf);
    }
}

// ---------------- fused GN + GELU + 5x5 depthwise conv ----------------
__global__ void dwconv_fused_kernel(const float* __restrict__ gg,
                                    const float* __restrict__ gb,
                                    const float* __restrict__ Wdw) {
    __shared__ float sT[144][68];

    int tileid = blockIdx.x;
    int cg = blockIdx.y, b = blockIdx.z;
    int ty0 = (tileid / 5) * 8, tx0 = (tileid % 5) * 8;
    int tid = threadIdx.x;
    int ch  = tid & 63;
    int chg = cg*64 + ch;

    float gamma = gg[chg], beta = gb[chg];
    int grp = chg >> 5;
    float mu = g_gnm[(b*GNg + grp)*2];
    float rs = g_gnm[(b*GNg + grp)*2 + 1];

    float wreg[25];
    #pragma unroll
    for (int i = 0; i < 25; i++) wreg[i] = Wdw[chg*25 + i];

    for (int i = tid; i < 144*64; i += 256) {
        int pos = i >> 6;
        int wy = pos / 12, wx = pos - (pos/12)*12;
        int y = ty0 + wy - 2, x = tx0 + wx - 2;
        float v = 0.f;
        if (y >= 0 && y < Hh && x >= 0 && x < Wd) {
            float hv = g_h1[(size_t)(b*HW + y*Wd + x)*HIDd + chg];
            hv = (hv - mu) * rs * gamma + beta;
            v = 0.5f * hv * (1.f + erff(hv * 0.70710678118654752f));
        }
        sT[pos][ch] = v;
    }
    __syncthreads();

    int pg = tid >> 6;
    #pragma unroll
    for (int p = 0; p < 16; p++) {
        int po = pg*16 + p;
        int y = po >> 3, x = po & 7;
        float acc = 0.f;
        #pragma unroll
        for (int dy = 0; dy < 5; dy++)
            #pragma unroll
            for (int dx = 0; dx < 5; dx++)
                acc += wreg[dy*5+dx] * sT[(y+dy)*12 + (x+dx)][ch];
        g_cv[(size_t)(b*HW + (ty0+y)*Wd + (tx0+x))*HIDd + chg] = acc;
    }
}

// ---------------- launch ----------------
extern "C" void kernel_launch(void* const* d_in, const int* in_sizes, int n_in,
                              void* d_out, int out_size) {
    const float* img   = (const float*)d_in[0];
    const float* imw   = (const float*)d_in[1];
    const float* msk   = (const float*)d_in[2];
    const float* ln1g  = (const float*)d_in[3];
    const float* ln1b  = (const float*)d_in[4];
    const float* ln2g  = (const float*)d_in[5];
    const float* ln2b  = (const float*)d_in[6];
    const float* Wq    = (const float*)d_in[7];
    const float* bq    = (const float*)d_in[8];
    const float* Wk    = (const float*)d_in[9];
    const float* bk    = (const float*)d_in[10];
    const float* Wv    = (const float*)d_in[11];
    const float* bv    = (const float*)d_in[12];
    const float* Wrel  = (const float*)d_in[13];
    const float* brel  = (const float*)d_in[14];
    const float* Wproj = (const float*)d_in[15];
    const float* bproj = (const float*)d_in[16];
    const float* W1    = (const float*)d_in[17];
    const float* bW1   = (const float*)d_in[18];
    const float* gng   = (const float*)d_in[19];
    const float* gnb   = (const float*)d_in[20];
    const float* Wdw   = (const float*)d_in[21];
    const float* W2    = (const float*)d_in[22];
    const float* bW2   = (const float*)d_in[23];
    float* out = (float*)d_out;

    float *qln, *kln, *vln, *Q, *K, *V, *att, *x1, *ln2, *h1, *cv;
    cudaGetSymbolAddress((void**)&qln, g_qln);
    cudaGetSymbolAddress((void**)&kln, g_kln);
    cudaGetSymbolAddress((void**)&vln, g_vln);
    cudaGetSymbolAddress((void**)&Q,   g_Q);
    cudaGetSymbolAddress((void**)&K,   g_K);
    cudaGetSymbolAddress((void**)&V,   g_V);
    cudaGetSymbolAddress((void**)&att, g_att);
    cudaGetSymbolAddress((void**)&x1,  g_x1);
    cudaGetSymbolAddress((void**)&ln2, g_ln2);
    cudaGetSymbolAddress((void**)&h1,  g_h1);
    cudaGetSymbolAddress((void**)&cv,  g_cv);

    int smem128 = (2*128*KP + 2*BN*KP) * sizeof(float);
    cudaFuncSetAttribute(mma_gemm_kernel<128>,
                         cudaFuncAttributeMaxDynamicSharedMemorySize, smem128);
    cudaFuncSetAttribute(mma_qkv_kernel,
                         cudaFuncAttributeMaxDynamicSharedMemorySize, smem128);

    // 1. LayerNorms
    ln3_kernel<<<TOK, 256>>>(img, imw, msk, ln1g, ln1b);

    // 2. QKV projections
    QKVArgs qa;
    qa.A[0] = qln; qa.A[1] = kln; qa.A[2] = vln;
    qa.W[0] = Wq;  qa.W[1] = Wk;  qa.W[2] = Wv;
    qa.bias[0] = bq; qa.bias[1] = bk; qa.bias[2] = bv;
    qa.C[0] = Q; qa.C[1] = K; qa.C[2] = V;
    mma_qkv_kernel<<<dim3(Cd/BN, TOK/128, 3), 256, smem128>>>(qa);

    // 3. tensor-core attention v2
    int attn_smem = (16*PKW + EXTP*PKW + 16*SSP + 16*PVW + 512
                     + 16*RELP + 16 + 228) * 4;
    cudaFuncSetAttribute(attn_tile_kernel,
                         cudaFuncAttributeMaxDynamicSharedMemorySize, attn_smem);
    attn_tile_kernel<<<dim3((Hh/QT)*(Wd/QT), NHd, Bz), 256, attn_smem>>>(Wrel, brel);

    // 4. output projection + fused residual -> x1
    mma_gemm_kernel<128><<<dim3(Cd/BN, TOK/128), 256, smem128>>>(att, Wproj, bproj, x1,
                                                                 Cd, Cd, 1, img);

    // 5. MLP branch
    ln_tok_kernel<<<TOK, 256>>>(ln2g, ln2b);
    mma_gemm_kernel<128><<<dim3(HIDd/BN, TOK/128), 256, smem128>>>(ln2, W1, bW1, h1,
                                                                   HIDd, Cd, 0, nullptr);
    gn_stats_kernel<<<Bz*GNg, 256>>>();
    dwconv_fused_kernel<<<dim3(25, HIDd/64, Bz), 256>>>(gng, gnb, Wdw);

    // 6. W2 + fused final residual + transpose to BCHW
    mma_gemm_kernel<128><<<dim3(Cd/BN, TOK/128), 256, smem128>>>(cv, W2, bW2, out,
                                                                 Cd, HIDd, 2, x1);
}

// round 15
// speedup vs baseline: 1.0225x; 1.0208x over previous
#include <cuda_runtime.h>
#include <cuda_bf16.h>
#include <math.h>

#define Bz   2
#define Cd   256
#define Hh   40
#define Wd   40
#define HW   1600
#define TOK  3200
#define NHd  8
#define HDd  32
#define WSd  15
#define W2Sd 225
#define MDd  7
#define HIDd 1024
#define GNg  32
#define EPSf 1e-5f
#define NEGINF -1e38f

// attention tiling (round-10 champion layout, bf16 rel)
#define QT    4
#define EXT   18
#define EXT2  (EXT*EXT)
#define KPAD  325          // bf16x2 row stride (channel-pair rows)
#define SPAD  228
#define RELB  240          // bf16 rel row stride

// GEMM tiling
#define BN 64
#define BK 32
#define KP 36

// ---------------- scratch ----------------
__device__ float g_qln[TOK*Cd];
__device__ float g_kln[TOK*Cd];
__device__ float g_vln[TOK*Cd];
__device__ float g_Q[TOK*Cd];
__device__ float g_K[TOK*Cd];
__device__ float g_V[TOK*Cd];
__device__ float g_att[TOK*Cd];
__device__ float g_x1[TOK*Cd];
__device__ float g_ln2[TOK*Cd];
__device__ float g_h1[TOK*HIDd];
__device__ float g_cv[TOK*HIDd];
__device__ float g_gnm[Bz*GNg*2];

// ---------------- block mean/var helper (256 threads) ----------------
__device__ __forceinline__ void block_meanvar(float v, float* sbuf,
                                              float& mu, float& rstd) {
    float s = v, q = v*v;
    #pragma unroll
    for (int d = 16; d > 0; d >>= 1) {
        s += __shfl_xor_sync(0xffffffffu, s, d);
        q += __shfl_xor_sync(0xffffffffu, q, d);
    }
    int warp = threadIdx.x >> 5, lane = threadIdx.x & 31;
    if (lane == 0) { sbuf[warp] = s; sbuf[8 + warp] = q; }
    __syncthreads();
    if (warp == 0) {
        float ss = (lane < 8) ? sbuf[lane] : 0.f;
        float qq = (lane < 8) ? sbuf[8 + lane] : 0.f;
        #pragma unroll
        for (int d = 4; d > 0; d >>= 1) {
            ss += __shfl_xor_sync(0xffffffffu, ss, d);
            qq += __shfl_xor_sync(0xffffffffu, qq, d);
        }
        if (lane == 0) {
            float m = ss * (1.0f/Cd);
            float var = qq * (1.0f/Cd) - m*m;
            sbuf[16] = m;
            sbuf[17] = rsqrtf(var + EPSf);
        }
    }
    __syncthreads();
    mu = sbuf[16]; rstd = sbuf[17];
}

// ---------------- fused LN of img / img_warp / img_warp+mask ----------------
__global__ void ln3_kernel(const float* __restrict__ img,
                           const float* __restrict__ imw,
                           const float* __restrict__ msk,
                           const float* __restrict__ g1,
                           const float* __restrict__ b1) {
    int tok = blockIdx.x;
    int c   = threadIdx.x;
    int b   = tok / HW, pos = tok % HW;
    int off = (b*Cd + c)*HW + pos;

    float x0 = img[off];
    float x1 = imw[off];
    float x2 = x1 + msk[off];
    float gg = g1[c], bb = b1[c];

    __shared__ float sbuf[18];
    float mu, rs;

    block_meanvar(x0, sbuf, mu, rs);
    g_qln[tok*Cd + c] = (x0 - mu) * rs * gg + bb;
    __syncthreads();
    block_meanvar(x1, sbuf, mu, rs);
    g_kln[tok*Cd + c] = (x1 - mu) * rs * gg + bb;
    __syncthreads();
    block_meanvar(x2, sbuf, mu, rs);
    g_vln[tok*Cd + c] = (x2 - mu) * rs * gg + bb;
}

__global__ void ln_tok_kernel(const float* __restrict__ g1,
                              const float* __restrict__ b1) {
    int tok = blockIdx.x;
    int c   = threadIdx.x;
    float v = g_x1[tok*Cd + c];
    __shared__ float sbuf[18];
    float mu, rs;
    block_meanvar(v, sbuf, mu, rs);
    g_ln2[tok*Cd + c] = (v - mu) * rs * g1[c] + b1[c];
}

// ---------------- tf32 helpers ----------------
__device__ __forceinline__ unsigned f2tf32(float x) {
    unsigned r;
    asm("cvt.rna.tf32.f32 %0, %1;" : "=r"(r) : "f"(x));
    return r;
}
__device__ __forceinline__ void mma_tf32(float& c0, float& c1, float& c2, float& c3,
                                         unsigned a0, unsigned a1, unsigned a2, unsigned a3,
                                         unsigned b0, unsigned b1) {
    asm volatile(
        "mma.sync.aligned.m16n8k8.row.col.f32.tf32.tf32.f32 "
        "{%0,%1,%2,%3}, {%4,%5,%6,%7}, {%8,%9}, {%0,%1,%2,%3};"
        : "+f"(c0), "+f"(c1), "+f"(c2), "+f"(c3)
        : "r"(a0), "r"(a1), "r"(a2), "r"(a3), "r"(b0), "r"(b1));
}
__device__ __forceinline__ void cp_async16(unsigned dst, const void* src) {
    asm volatile("cp.async.cg.shared.global [%0], [%1], 16;\n"
                 :: "r"(dst), "l"(src));
}
__device__ __forceinline__ void cp_commit() {
    asm volatile("cp.async.commit_group;\n");
}

// ---------------- tf32 GEMM, cp.async double buffered ----------
template<int BMT>
__device__ __forceinline__ void mma_body(const float* __restrict__ A, int lda,
                                         const float* __restrict__ Wt,
                                         const float* __restrict__ bias,
                                         float* __restrict__ C,
                                         int N, int K, int m0, int n0,
                                         int mode, const float* __restrict__ res) {
    constexpr int MT = BMT / 64;
    extern __shared__ float smem[];
    float* As = smem;
    float* Ws = smem + 2*BMT*KP;

    int tid  = threadIdx.x;
    int lane = tid & 31, warp = tid >> 5;
    int wm = (warp >> 1) * (16*MT), wn = (warp & 1) * 32;
    int g = lane >> 2, t4 = lane & 3;

    float acc[MT][4][4] = {};
    int steps = K / BK;

    unsigned sA = (unsigned)__cvta_generic_to_shared(As);
    unsigned sW = (unsigned)__cvta_generic_to_shared(Ws);

    auto load_stage = [&](int kc, int s) {
        int k0 = kc * BK;
        #pragma unroll
        for (int it = 0; it < BMT/32; it++) {
            int idx = tid + it*256;
            int row = idx >> 3, ch = (idx & 7) * 4;
            cp_async16(sA + (unsigned)(((s*BMT + row)*KP + ch) * 4),
                       &A[(size_t)(m0+row)*lda + k0 + ch]);
        }
        #pragma unroll
        for (int it = 0; it < 2; it++) {
            int idx = tid + it*256;
            int row = idx >> 3, ch = (idx & 7) * 4;
            cp_async16(sW + (unsigned)(((s*BN + row)*KP + ch) * 4),
                       &Wt[(size_t)(n0+row)*K + k0 + ch]);
        }
        cp_commit();
    };

    load_stage(0, 0);

    for (int kc = 0; kc < steps; kc++) {
        int s = kc & 1;
        if (kc + 1 < steps) {
            load_stage(kc + 1, (kc + 1) & 1);
            asm volatile("cp.async.wait_group 1;\n");
        } else {
            asm volatile("cp.async.wait_group 0;\n");
        }
        __syncthreads();

        float* Ab = As + s*BMT*KP;
        float* Wb = Ws + s*BN*KP;
        #pragma unroll
        for (int ks = 0; ks < BK; ks += 8) {
            unsigned a[MT][4], bf[4][2];
            #pragma unroll
            for (int mt = 0; mt < MT; mt++) {
                int rb = wm + mt*16;
                a[mt][0] = f2tf32(Ab[(rb + g    )*KP + ks + t4    ]);
                a[mt][1] = f2tf32(Ab[(rb + g + 8)*KP + ks + t4    ]);
                a[mt][2] = f2tf32(Ab[(rb + g    )*KP + ks + t4 + 4]);
                a[mt][3] = f2tf32(Ab[(rb + g + 8)*KP + ks + t4 + 4]);
            }
            #pragma unroll
            for (int nt = 0; nt < 4; nt++) {
                int nb = wn + nt*8 + g;
                bf[nt][0] = f2tf32(Wb[nb*KP + ks + t4    ]);
                bf[nt][1] = f2tf32(Wb[nb*KP + ks + t4 + 4]);
            }
            #pragma unroll
            for (int mt = 0; mt < MT; mt++)
                #pragma unroll
                for (int nt = 0; nt < 4; nt++)
                    mma_tf32(acc[mt][nt][0], acc[mt][nt][1],
                             acc[mt][nt][2], acc[mt][nt][3],
                             a[mt][0], a[mt][1], a[mt][2], a[mt][3],
                             bf[nt][0], bf[nt][1]);
        }
        __syncthreads();
    }

    #pragma unroll
    for (int mt = 0; mt < MT; mt++) {
        #pragma unroll
        for (int nt = 0; nt < 4; nt++) {
            #pragma unroll
            for (int i = 0; i < 4; i++) {
                int mrow = m0 + wm + mt*16 + g + ((i >= 2) ? 8 : 0);
                int ncol = n0 + wn + nt*8 + 2*t4 + (i & 1);
                float v = acc[mt][nt][i] + bias[ncol];
                if (mode == 0) {
                    C[(size_t)mrow*N + ncol] = v;
                } else if (mode == 1) {
                    int b = mrow / HW, pos = mrow % HW;
                    C[(size_t)mrow*N + ncol] =
                        v + res[(size_t)(b*Cd + ncol)*HW + pos];
                } else {
                    int b = mrow / HW, pos = mrow % HW;
                    C[(size_t)(b*Cd + ncol)*HW + pos] =
                        v + res[(size_t)mrow*N + ncol];
                }
            }
        }
    }
}

template<int BMT>
__global__ void mma_gemm_kernel(const float* __restrict__ A,
                                const float* __restrict__ Wt,
                                const float* __restrict__ bias,
                                float* __restrict__ C,
                                int N, int K, int mode,
                                const float* __restrict__ res) {
    mma_body<BMT>(A, K, Wt, bias, C, N, K, blockIdx.y*BMT, blockIdx.x*BN, mode, res);
}

struct QKVArgs {
    const float* A[3];
    const float* W[3];
    const float* bias[3];
    float* C[3];
};
__global__ void mma_qkv_kernel(QKVArgs args) {
    int z = blockIdx.z;
    mma_body<128>(args.A[z], Cd, args.W[z], args.bias[z], args.C[z],
                  Cd, Cd, blockIdx.y*128, blockIdx.x*BN, 0, nullptr);
}

// ---------------- tiled local attention (round-10 + bf16 rel) -------------
__global__ void attn_tile_kernel(const float* __restrict__ Wrel,
                                 const float* __restrict__ brel) {
    extern __shared__ float smem[];
    __nv_bfloat162* sKh = (__nv_bfloat162*)smem;           // [16 c2][KPAD]
    float* sS = smem + 16*KPAD;                            // [16][SPAD]
    __nv_bfloat16* sRelh = (__nv_bfloat16*)(sS + 16*SPAD); // [16][RELB]
    float* sInv = (float*)(sRelh + 16*RELB);               // [16]

    int tile = blockIdx.x;
    int h = blockIdx.y, b = blockIdx.z;
    int ty0 = (tile / (Wd/QT)) * QT;
    int tx0 = (tile % (Wd/QT)) * QT;
    int t = threadIdx.x;
    int lane = t & 31, warp = t >> 5;
    int g = lane >> 2, t4 = lane & 3;

    // ---- rel MMA prologue: sRelh[16q][225o] = Qtile x Wrel[h]^T + brel ----
    {
        unsigned aq[4][4];
        int q0 = g, q1 = g + 8;
        int tk0 = b*HW + (ty0 + (q0 >> 2))*Wd + tx0 + (q0 & 3);
        int tk1 = b*HW + (ty0 + (q1 >> 2))*Wd + tx0 + (q1 & 3);
        const float* Q0 = g_Q + (size_t)tk0*Cd + h*HDd;
        const float* Q1 = g_Q + (size_t)tk1*Cd + h*HDd;
        #pragma unroll
        for (int ks = 0; ks < 4; ks++) {
            aq[ks][0] = f2tf32(Q0[ks*8 + t4]);
            aq[ks][1] = f2tf32(Q1[ks*8 + t4]);
            aq[ks][2] = f2tf32(Q0[ks*8 + t4 + 4]);
            aq[ks][3] = f2tf32(Q1[ks*8 + t4 + 4]);
        }
        const float* Wh = Wrel + (size_t)h*W2Sd*HDd;
        for (int nt = warp; nt < 29; nt += 8) {
            int n0 = nt*8;
            int o = n0 + g;
            float c0 = 0.f, c1 = 0.f, c2 = 0.f, c3 = 0.f;
            #pragma unroll
            for (int ks = 0; ks < 4; ks++) {
                float w0 = 0.f, w1 = 0.f;
                if (o < W2Sd) {
                    w0 = Wh[o*HDd + ks*8 + t4];
                    w1 = Wh[o*HDd + ks*8 + t4 + 4];
                }
                mma_tf32(c0, c1, c2, c3,
                         aq[ks][0], aq[ks][1], aq[ks][2], aq[ks][3],
                         f2tf32(w0), f2tf32(w1));
            }
            int o0 = n0 + 2*t4, o1 = o0 + 1;
            float br0 = (o0 < W2Sd) ? brel[h*W2Sd + o0] : 0.f;
            float br1 = (o1 < W2Sd) ? brel[h*W2Sd + o1] : 0.f;
            sRelh[g*RELB + o0]     = __float2bfloat16(c0 + br0);
            sRelh[g*RELB + o1]     = __float2bfloat16(c1 + br1);
            sRelh[(g+8)*RELB + o0] = __float2bfloat16(c2 + br0);
            sRelh[(g+8)*RELB + o1] = __float2bfloat16(c3 + br1);
        }
    }

    // ---- K window load: bf16x2 channel pairs, zero-padded OOB ----
    int wy0 = ty0 - MDd, wx0 = tx0 - MDd;
    for (int i = t; i < EXT2*16; i += 256) {
        int pos = i >> 4, c2 = i & 15;
        int wy = pos / EXT, wx = pos - (pos/EXT)*EXT;
        int ky = wy0 + wy, kx = wx0 + wx;
        float2 v = make_float2(0.f, 0.f);
        if (ky >= 0 && ky < Hh && kx >= 0 && kx < Wd)
            v = *(const float2*)(g_K + (size_t)(b*HW + ky*Wd + kx)*Cd + h*HDd + c2*2);
        sKh[c2*KPAD + pos] = __float22bfloat162_rn(v);
    }
    __syncthreads();

    // ---- score loop ----
    int q  = t >> 4;
    int lo = t & 15;
    int qy = q >> 2, qx = q & 3;
    int ty = ty0 + qy, tx = tx0 + qx;
    int tok = b*HW + ty*Wd + tx;
    float qreg[32];
    {
        const float* qp = g_Q + (size_t)tok*Cd + h*HDd;
        #pragma unroll
        for (int c = 0; c < 32; c++) qreg[c] = qp[c];
    }

    const float scale = 0.17677669529663687f;
    for (int o = lo; o < W2Sd; o += 16) {
        int oy = o / WSd, ox = o - (o/WSd)*WSd;
        int ky = ty + oy - MDd, kx = tx + ox - MDd;
        float s = NEGINF;
        if (ky >= 0 && ky < Hh && kx >= 0 && kx < Wd) {
            int pos = (qy + oy)*EXT + (qx + ox);
            float d = 0.f;
            #pragma unroll
            for (int c2 = 0; c2 < 16; c2++) {
                float2 kv = __bfloat1622float2(sKh[c2*KPAD + pos]);
                d += qreg[2*c2]*kv.x + qreg[2*c2+1]*kv.y;
            }
            s = d*scale + __bfloat162float(sRelh[q*RELB + o]);
        }
        sS[q*SPAD + o] = s;
    }
    __syncthreads();

    // ---- softmax ----
    {
        float mx = NEGINF;
        for (int o = lo; o < W2Sd; o += 16)
            mx = fmaxf(mx, sS[q*SPAD + o]);
        #pragma unroll
        for (int d = 8; d > 0; d >>= 1)
            mx = fmaxf(mx, __shfl_xor_sync(0xffffffffu, mx, d));
        float sum = 0.f;
        for (int o = lo; o < W2Sd; o += 16) {
            float s = sS[q*SPAD + o];
            float e = (s > -1e37f) ? __expf(s - mx) : 0.f;
            sS[q*SPAD + o] = e;
            sum += e;
        }
        #pragma unroll
        for (int d = 8; d > 0; d >>= 1)
            sum += __shfl_xor_sync(0xffffffffu, sum, d);
        if (lo == 0) sInv[q] = 1.f / sum;
    }
    __syncthreads();

    // ---- V window (reuse sKh, bf16x2) ----
    for (int i = t; i < EXT2*16; i += 256) {
        int pos = i >> 4, c2 = i & 15;
        int wy = pos / EXT, wx = pos - (pos/EXT)*EXT;
        int ky = wy0 + wy, kx = wx0 + wx;
        float2 v = make_float2(0.f, 0.f);
        if (ky >= 0 && ky < Hh && kx >= 0 && kx < Wd)
            v = *(const float2*)(g_V + (size_t)(b*HW + ky*Wd + kx)*Cd + h*HDd + c2*2);
        sKh[c2*KPAD + pos] = __float22bfloat162_rn(v);
    }
    __syncthreads();

    // ---- weighted V sum: thread = (query, channel pair) ----
    {
        int c2 = t & 15;
        float ax = 0.f, ay = 0.f;
        #pragma unroll
        for (int oy = 0; oy < WSd; oy++) {
            int pos0 = (qy + oy)*EXT + qx;
            int srow = q*SPAD + oy*WSd;
            #pragma unroll
            for (int ox = 0; ox < WSd; ox++) {
                float p = sS[srow + ox];
                float2 v = __bfloat1622float2(sKh[c2*KPAD + pos0 + ox]);
                ax += p*v.x;
                ay += p*v.y;
            }
        }
        float inv = sInv[q];
        float2 o2 = make_float2(ax*inv, ay*inv);
        *(float2*)(g_att + (size_t)tok*Cd + h*HDd + c2*2) = o2;
    }
}

// ---------------- GroupNorm stats per (b, group) ----------------
__global__ void gn_stats_kernel() {
    int bg = blockIdx.x;
    int b = bg / GNg, g = bg % GNg;
    int tid = threadIdx.x;
    float sm = 0.f, sq = 0.f;
    for (int i = tid; i < HW*32; i += 256) {
        int ch  = g*32 + (i & 31);
        int pos = i >> 5;
        float v = g_h1[(size_t)(b*HW + pos)*HIDd + ch];
        sm += v; sq += v*v;
    }
    #pragma unroll
    for (int d = 16; d > 0; d >>= 1) {
        sm += __shfl_xor_sync(0xffffffffu, sm, d);
        sq += __shfl_xor_sync(0xffffffffu, sq, d);
    }
    __shared__ float s1[8], s2[8];
    int warp = tid >> 5, lane = tid & 31;
    if (lane == 0) { s1[warp] = sm; s2[warp] = sq; }
    __syncthreads();
    if (tid == 0) {
        float ss = 0.f, qq = 0.f;
        #pragma unroll
        for (int i = 0; i < 8; i++) { ss += s1[i]; qq += s2[i]; }
        float cnt = (float)(HW*32);
        float mu  = ss / cnt;
        float var = qq / cnt - mu*mu;
        g_gnm[bg*2]   = mu;
        g_gnm[bg*2+1] = rsqrtf(var + EPSf);
    }
}

// ---------------- fused GN + GELU + 5x5 depthwise conv ----------------
__global__ void dwconv_fused_kernel(const float* __restrict__ gg,
                                    const float* __restrict__ gb,
                                    const float* __restrict__ Wdw) {
    __shared__ float sT[144][68];

    int tileid = blockIdx.x;
    int cg = blockIdx.y, b = blockIdx.z;
    int ty0 = (tileid / 5) * 8, tx0 = (tileid % 5) * 8;
    int tid = threadIdx.x;
    int ch  = tid & 63;
    int chg = cg*64 + ch;

    float gamma = gg[chg], beta = gb[chg];
    int grp = chg >> 5;
    float mu = g_gnm[(b*GNg + grp)*2];
    float rs = g_gnm[(b*GNg + grp)*2 + 1];

    float wreg[25];
    #pragma unroll
    for (int i = 0; i < 25; i++) wreg[i] = Wdw[chg*25 + i];

    for (int i = tid; i < 144*64; i += 256) {
        int pos = i >> 6;
        int wy = pos / 12, wx = pos - (pos/12)*12;
        int y = ty0 + wy - 2, x = tx0 + wx - 2;
        float v = 0.f;
        if (y >= 0 && y < Hh && x >= 0 && x < Wd) {
            float hv = g_h1[(size_t)(b*HW + y*Wd + x)*HIDd + chg];
            hv = (hv - mu) * rs * gamma + beta;
            v = 0.5f * hv * (1.f + erff(hv * 0.70710678118654752f));
        }
        sT[pos][ch] = v;
    }
    __syncthreads();

    int pg = tid >> 6;
    #pragma unroll
    for (int p = 0; p < 16; p++) {
        int po = pg*16 + p;
        int y = po >> 3, x = po & 7;
        float acc = 0.f;
        #pragma unroll
        for (int dy = 0; dy < 5; dy++)
            #pragma unroll
            for (int dx = 0; dx < 5; dx++)
                acc += wreg[dy*5+dx] * sT[(y+dy)*12 + (x+dx)][ch];
        g_cv[(size_t)(b*HW + (ty0+y)*Wd + (tx0+x))*HIDd + chg] = acc;
    }
}

// ---------------- launch ----------------
extern "C" void kernel_launch(void* const* d_in, const int* in_sizes, int n_in,
                              void* d_out, int out_size) {
    const float* img   = (const float*)d_in[0];
    const float* imw   = (const float*)d_in[1];
    const float* msk   = (const float*)d_in[2];
    const float* ln1g  = (const float*)d_in[3];
    const float* ln1b  = (const float*)d_in[4];
    const float* ln2g  = (const float*)d_in[5];
    const float* ln2b  = (const float*)d_in[6];
    const float* Wq    = (const float*)d_in[7];
    const float* bq    = (const float*)d_in[8];
    const float* Wk    = (const float*)d_in[9];
    const float* bk    = (const float*)d_in[10];
    const float* Wv    = (const float*)d_in[11];
    const float* bv    = (const float*)d_in[12];
    const float* Wrel  = (const float*)d_in[13];
    const float* brel  = (const float*)d_in[14];
    const float* Wproj = (const float*)d_in[15];
    const float* bproj = (const float*)d_in[16];
    const float* W1    = (const float*)d_in[17];
    const float* bW1   = (const float*)d_in[18];
    const float* gng   = (const float*)d_in[19];
    const float* gnb   = (const float*)d_in[20];
    const float* Wdw   = (const float*)d_in[21];
    const float* W2    = (const float*)d_in[22];
    const float* bW2   = (const float*)d_in[23];
    float* out = (float*)d_out;

    float *qln, *kln, *vln, *Q, *K, *V, *att, *x1, *ln2, *h1, *cv;
    cudaGetSymbolAddress((void**)&qln, g_qln);
    cudaGetSymbolAddress((void**)&kln, g_kln);
    cudaGetSymbolAddress((void**)&vln, g_vln);
    cudaGetSymbolAddress((void**)&Q,   g_Q);
    cudaGetSymbolAddress((void**)&K,   g_K);
    cudaGetSymbolAddress((void**)&V,   g_V);
    cudaGetSymbolAddress((void**)&att, g_att);
    cudaGetSymbolAddress((void**)&x1,  g_x1);
    cudaGetSymbolAddress((void**)&ln2, g_ln2);
    cudaGetSymbolAddress((void**)&h1,  g_h1);
    cudaGetSymbolAddress((void**)&cv,  g_cv);

    int smem128 = (2*128*KP + 2*BN*KP) * sizeof(float);
    cudaFuncSetAttribute(mma_gemm_kernel<128>,
                         cudaFuncAttributeMaxDynamicSharedMemorySize, smem128);
    cudaFuncSetAttribute(mma_qkv_kernel,
                         cudaFuncAttributeMaxDynamicSharedMemorySize, smem128);

    // 1. LayerNorms
    ln3_kernel<<<TOK, 256>>>(img, imw, msk, ln1g, ln1b);

    // 2. QKV projections
    QKVArgs qa;
    qa.A[0] = qln; qa.A[1] = kln; qa.A[2] = vln;
    qa.W[0] = Wq;  qa.W[1] = Wk;  qa.W[2] = Wv;
    qa.bias[0] = bq; qa.bias[1] = bk; qa.bias[2] = bv;
    qa.C[0] = Q; qa.C[1] = K; qa.C[2] = V;
    mma_qkv_kernel<<<dim3(Cd/BN, TOK/128, 3), 256, smem128>>>(qa);

    // 3. tiled windowed attention (43.1KB smem -> 5 blocks/SM)
    int attn_smem = (16*KPAD + 16*SPAD) * 4 + 16*RELB*2 + 64;
    cudaFuncSetAttribute(attn_tile_kernel,
                         cudaFuncAttributeMaxDynamicSharedMemorySize, attn_smem);
    attn_tile_kernel<<<dim3((Hh/QT)*(Wd/QT), NHd, Bz), 256, attn_smem>>>(Wrel, brel);

    // 4. output projection + fused residual -> x1
    mma_gemm_kernel<128><<<dim3(Cd/BN, TOK/128), 256, smem128>>>(att, Wproj, bproj, x1,
                                                                 Cd, Cd, 1, img);

    // 5. MLP branch
    ln_tok_kernel<<<TOK, 256>>>(ln2g, ln2b);
    mma_gemm_kernel<128><<<dim3(HIDd/BN, TOK/128), 256, smem128>>>(ln2, W1, bW1, h1,
                                                                   HIDd, Cd, 0, nullptr);
    gn_stats_kernel<<<Bz*GNg, 256>>>();
    dwconv_fused_kernel<<<dim3(25, HIDd/64, Bz), 256>>>(gng, gnb, Wdw);

    // 6. W2 + fused final residual + transpose to BCHW
    mma_gemm_kernel<128><<<dim3(Cd/BN, TOK/128), 256, smem128>>>(cv, W2, bW2, out,
                                                                 Cd, HIDd, 2, x1);
}

// round 16
// speedup vs baseline: 1.0523x; 1.0291x over previous
#include <cuda_runtime.h>
#include <cuda_bf16.h>
#include <math.h>

#define Bz   2
#define Cd   256
#define Hh   40
#define Wd   40
#define HW   1600
#define TOK  3200
#define NHd  8
#define HDd  32
#define WSd  15
#define W2Sd 225
#define MDd  7
#define HIDd 1024
#define GNg  32
#define EPSf 1e-5f
#define NEGINF -1e38f

// attention MMA tiling
#define QT    4
#define EXT   18
#define EXT2  (EXT*EXT)    // 324
#define EXTP  336          // padded to 21 k16 steps
#define PKW   20           // K row stride (u32 words), [pos][ch-pairs]
#define PVW   172          // P/V row stride (u32 words) — conflict-free (12g+t4)
#define SSP   340          // score row stride (fp32)
#define RELB  240          // bf16 rel row stride
#define NBIG  8256         // union region: max(336*20, 16*172 + 32*172)

// GEMM tiling
#define BN 64
#define BK 32
#define KP 36

// ---------------- scratch ----------------
__device__ float g_qln[TOK*Cd];
__device__ float g_kln[TOK*Cd];
__device__ float g_vln[TOK*Cd];
__device__ float g_Q[TOK*Cd];
__device__ float g_K[TOK*Cd];
__device__ float g_V[TOK*Cd];
__device__ float g_att[TOK*Cd];
__device__ float g_x1[TOK*Cd];
__device__ float g_ln2[TOK*Cd];
__device__ float g_h1[TOK*HIDd];
__device__ float g_cv[TOK*HIDd];
__device__ float g_gnm[Bz*GNg*2];

// ---------------- block mean/var helper (256 threads) ----------------
__device__ __forceinline__ void block_meanvar(float v, float* sbuf,
                                              float& mu, float& rstd) {
    float s = v, q = v*v;
    #pragma unroll
    for (int d = 16; d > 0; d >>= 1) {
        s += __shfl_xor_sync(0xffffffffu, s, d);
        q += __shfl_xor_sync(0xffffffffu, q, d);
    }
    int warp = threadIdx.x >> 5, lane = threadIdx.x & 31;
    if (lane == 0) { sbuf[warp] = s; sbuf[8 + warp] = q; }
    __syncthreads();
    if (warp == 0) {
        float ss = (lane < 8) ? sbuf[lane] : 0.f;
        float qq = (lane < 8) ? sbuf[8 + lane] : 0.f;
        #pragma unroll
        for (int d = 4; d > 0; d >>= 1) {
            ss += __shfl_xor_sync(0xffffffffu, ss, d);
            qq += __shfl_xor_sync(0xffffffffu, qq, d);
        }
        if (lane == 0) {
            float m = ss * (1.0f/Cd);
            float var = qq * (1.0f/Cd) - m*m;
            sbuf[16] = m;
            sbuf[17] = rsqrtf(var + EPSf);
        }
    }
    __syncthreads();
    mu = sbuf[16]; rstd = sbuf[17];
}

// ---------------- fused LN of img / img_warp / img_warp+mask ----------------
__global__ void ln3_kernel(const float* __restrict__ img,
                           const float* __restrict__ imw,
                           const float* __restrict__ msk,
                           const float* __restrict__ g1,
                           const float* __restrict__ b1) {
    int tok = blockIdx.x;
    int c   = threadIdx.x;
    int b   = tok / HW, pos = tok % HW;
    int off = (b*Cd + c)*HW + pos;

    float x0 = img[off];
    float x1 = imw[off];
    float x2 = x1 + msk[off];
    float gg = g1[c], bb = b1[c];

    __shared__ float sbuf[18];
    float mu, rs;

    block_meanvar(x0, sbuf, mu, rs);
    g_qln[tok*Cd + c] = (x0 - mu) * rs * gg + bb;
    __syncthreads();
    block_meanvar(x1, sbuf, mu, rs);
    g_kln[tok*Cd + c] = (x1 - mu) * rs * gg + bb;
    __syncthreads();
    block_meanvar(x2, sbuf, mu, rs);
    g_vln[tok*Cd + c] = (x2 - mu) * rs * gg + bb;
}

__global__ void ln_tok_kernel(const float* __restrict__ g1,
                              const float* __restrict__ b1) {
    int tok = blockIdx.x;
    int c   = threadIdx.x;
    float v = g_x1[tok*Cd + c];
    __shared__ float sbuf[18];
    float mu, rs;
    block_meanvar(v, sbuf, mu, rs);
    g_ln2[tok*Cd + c] = (v - mu) * rs * g1[c] + b1[c];
}

// ---------------- MMA helpers ----------------
__device__ __forceinline__ unsigned f2tf32(float x) {
    unsigned r;
    asm("cvt.rna.tf32.f32 %0, %1;" : "=r"(r) : "f"(x));
    return r;
}
__device__ __forceinline__ void mma_tf32(float& c0, float& c1, float& c2, float& c3,
                                         unsigned a0, unsigned a1, unsigned a2, unsigned a3,
                                         unsigned b0, unsigned b1) {
    asm volatile(
        "mma.sync.aligned.m16n8k8.row.col.f32.tf32.tf32.f32 "
        "{%0,%1,%2,%3}, {%4,%5,%6,%7}, {%8,%9}, {%0,%1,%2,%3};"
        : "+f"(c0), "+f"(c1), "+f"(c2), "+f"(c3)
        : "r"(a0), "r"(a1), "r"(a2), "r"(a3), "r"(b0), "r"(b1));
}
__device__ __forceinline__ void mma_bf16(float& c0, float& c1, float& c2, float& c3,
                                         unsigned a0, unsigned a1, unsigned a2, unsigned a3,
                                         unsigned b0, unsigned b1) {
    asm volatile(
        "mma.sync.aligned.m16n8k16.row.col.f32.bf16.bf16.f32 "
        "{%0,%1,%2,%3}, {%4,%5,%6,%7}, {%8,%9}, {%0,%1,%2,%3};"
        : "+f"(c0), "+f"(c1), "+f"(c2), "+f"(c3)
        : "r"(a0), "r"(a1), "r"(a2), "r"(a3), "r"(b0), "r"(b1));
}
__device__ __forceinline__ void cp_async16(unsigned dst, const void* src) {
    asm volatile("cp.async.cg.shared.global [%0], [%1], 16;\n"
                 :: "r"(dst), "l"(src));
}
__device__ __forceinline__ void cp_commit() {
    asm volatile("cp.async.commit_group;\n");
}

// ---------------- tf32 GEMM, cp.async double buffered ----------
template<int BMT>
__device__ __forceinline__ void mma_body(const float* __restrict__ A, int lda,
                                         const float* __restrict__ Wt,
                                         const float* __restrict__ bias,
                                         float* __restrict__ C,
                                         int N, int K, int m0, int n0,
                                         int mode, const float* __restrict__ res) {
    constexpr int MT = BMT / 64;
    extern __shared__ float smem[];
    float* As = smem;
    float* Ws = smem + 2*BMT*KP;

    int tid  = threadIdx.x;
    int lane = tid & 31, warp = tid >> 5;
    int wm = (warp >> 1) * (16*MT), wn = (warp & 1) * 32;
    int g = lane >> 2, t4 = lane & 3;

    float acc[MT][4][4] = {};
    int steps = K / BK;

    unsigned sA = (unsigned)__cvta_generic_to_shared(As);
    unsigned sW = (unsigned)__cvta_generic_to_shared(Ws);

    auto load_stage = [&](int kc, int s) {
        int k0 = kc * BK;
        #pragma unroll
        for (int it = 0; it < BMT/32; it++) {
            int idx = tid + it*256;
            int row = idx >> 3, ch = (idx & 7) * 4;
            cp_async16(sA + (unsigned)(((s*BMT + row)*KP + ch) * 4),
                       &A[(size_t)(m0+row)*lda + k0 + ch]);
        }
        #pragma unroll
        for (int it = 0; it < 2; it++) {
            int idx = tid + it*256;
            int row = idx >> 3, ch = (idx & 7) * 4;
            cp_async16(sW + (unsigned)(((s*BN + row)*KP + ch) * 4),
                       &Wt[(size_t)(n0+row)*K + k0 + ch]);
        }
        cp_commit();
    };

    load_stage(0, 0);

    for (int kc = 0; kc < steps; kc++) {
        int s = kc & 1;
        if (kc + 1 < steps) {
            load_stage(kc + 1, (kc + 1) & 1);
            asm volatile("cp.async.wait_group 1;\n");
        } else {
            asm volatile("cp.async.wait_group 0;\n");
        }
        __syncthreads();

        float* Ab = As + s*BMT*KP;
        float* Wb = Ws + s*BN*KP;
        #pragma unroll
        for (int ks = 0; ks < BK; ks += 8) {
            unsigned a[MT][4], bf[4][2];
            #pragma unroll
            for (int mt = 0; mt < MT; mt++) {
                int rb = wm + mt*16;
                a[mt][0] = f2tf32(Ab[(rb + g    )*KP + ks + t4    ]);
                a[mt][1] = f2tf32(Ab[(rb + g + 8)*KP + ks + t4    ]);
                a[mt][2] = f2tf32(Ab[(rb + g    )*KP + ks + t4 + 4]);
                a[mt][3] = f2tf32(Ab[(rb + g + 8)*KP + ks + t4 + 4]);
            }
            #pragma unroll
            for (int nt = 0; nt < 4; nt++) {
                int nb = wn + nt*8 + g;
                bf[nt][0] = f2tf32(Wb[nb*KP + ks + t4    ]);
                bf[nt][1] = f2tf32(Wb[nb*KP + ks + t4 + 4]);
            }
            #pragma unroll
            for (int mt = 0; mt < MT; mt++)
                #pragma unroll
                for (int nt = 0; nt < 4; nt++)
                    mma_tf32(acc[mt][nt][0], acc[mt][nt][1],
                             acc[mt][nt][2], acc[mt][nt][3],
                             a[mt][0], a[mt][1], a[mt][2], a[mt][3],
                             bf[nt][0], bf[nt][1]);
        }
        __syncthreads();
    }

    #pragma unroll
    for (int mt = 0; mt < MT; mt++) {
        #pragma unroll
        for (int nt = 0; nt < 4; nt++) {
            #pragma unroll
            for (int i = 0; i < 4; i++) {
                int mrow = m0 + wm + mt*16 + g + ((i >= 2) ? 8 : 0);
                int ncol = n0 + wn + nt*8 + 2*t4 + (i & 1);
                float v = acc[mt][nt][i] + bias[ncol];
                if (mode == 0) {
                    C[(size_t)mrow*N + ncol] = v;
                } else if (mode == 1) {
                    int b = mrow / HW, pos = mrow % HW;
                    C[(size_t)mrow*N + ncol] =
                        v + res[(size_t)(b*Cd + ncol)*HW + pos];
                } else {
                    int b = mrow / HW, pos = mrow % HW;
                    C[(size_t)(b*Cd + ncol)*HW + pos] =
                        v + res[(size_t)mrow*N + ncol];
                }
            }
        }
    }
}

template<int BMT>
__global__ void mma_gemm_kernel(const float* __restrict__ A,
                                const float* __restrict__ Wt,
                                const float* __restrict__ bias,
                                float* __restrict__ C,
                                int N, int K, int mode,
                                const float* __restrict__ res) {
    mma_body<BMT>(A, K, Wt, bias, C, N, K, blockIdx.y*BMT, blockIdx.x*BN, mode, res);
}

struct QKVArgs {
    const float* A[3];
    const float* W[3];
    const float* bias[3];
    float* C[3];
};
__global__ void mma_qkv_kernel(QKVArgs args) {
    int z = blockIdx.z;
    mma_body<128>(args.A[z], Cd, args.W[z], args.bias[z], args.C[z],
                  Cd, Cd, blockIdx.y*128, blockIdx.x*BN, 0, nullptr);
}

// ---------------- tensor-core local attention v3 (compact smem) -----------
// layout (words): sQ[0,320) | sBig[320,8576) | sS[8576,14016) |
//                 sRed[14016,14528) | sRelh(bf16)[14528,16448) | sInv[16448,16464)
// sBig holds K (336x20) during score phase, then P(16x172)+V(32x172) after.
__global__ void attn_tile_kernel(const float* __restrict__ Wrel,
                                 const float* __restrict__ brel) {
    extern __shared__ float smem[];
    unsigned* sQ   = (unsigned*)smem;
    unsigned* sBig = sQ + 16*PKW;
    float*    sS   = (float*)(sBig + NBIG);
    float*    sRed = sS + 16*SSP;
    __nv_bfloat16* sRelh = (__nv_bfloat16*)(sRed + 512);
    float*    sInv = (float*)(sRelh + 16*RELB);

    unsigned* sP = sBig;              // [16 q][PVW]   (after score phase)
    unsigned* sV = sBig + 16*PVW;     // [32 ch][PVW]

    int tile = blockIdx.x;
    int h = blockIdx.y, b = blockIdx.z;
    int ty0 = (tile / (Wd/QT)) * QT;
    int tx0 = (tile % (Wd/QT)) * QT;
    int t = threadIdx.x;
    int lane = t & 31, warp = t >> 5;
    int g = lane >> 2, t4 = lane & 3;

    const float scale = 0.17677669529663687f;
    int wy0 = ty0 - MDd, wx0 = tx0 - MDd;

    // ---- rel MMA prologue: sRelh[16q][225o] = Qtile x Wrel[h]^T + brel ----
    {
        unsigned aq[4][4];
        int q0 = g, q1 = g + 8;
        int tk0 = b*HW + (ty0 + (q0 >> 2))*Wd + tx0 + (q0 & 3);
        int tk1 = b*HW + (ty0 + (q1 >> 2))*Wd + tx0 + (q1 & 3);
        const float* Q0 = g_Q + (size_t)tk0*Cd + h*HDd;
        const float* Q1 = g_Q + (size_t)tk1*Cd + h*HDd;
        #pragma unroll
        for (int ks = 0; ks < 4; ks++) {
            aq[ks][0] = f2tf32(Q0[ks*8 + t4]);
            aq[ks][1] = f2tf32(Q1[ks*8 + t4]);
            aq[ks][2] = f2tf32(Q0[ks*8 + t4 + 4]);
            aq[ks][3] = f2tf32(Q1[ks*8 + t4 + 4]);
        }
        const float* Wh = Wrel + (size_t)h*W2Sd*HDd;
        for (int nt = warp; nt < 29; nt += 8) {
            int n0 = nt*8;
            int o = n0 + g;
            float c0 = 0.f, c1 = 0.f, c2 = 0.f, c3 = 0.f;
            #pragma unroll
            for (int ks = 0; ks < 4; ks++) {
                float w0 = 0.f, w1 = 0.f;
                if (o < W2Sd) {
                    w0 = Wh[o*HDd + ks*8 + t4];
                    w1 = Wh[o*HDd + ks*8 + t4 + 4];
                }
                mma_tf32(c0, c1, c2, c3,
                         aq[ks][0], aq[ks][1], aq[ks][2], aq[ks][3],
                         f2tf32(w0), f2tf32(w1));
            }
            int o0 = n0 + 2*t4, o1 = o0 + 1;
            float br0 = (o0 < W2Sd) ? brel[h*W2Sd + o0] : 0.f;
            float br1 = (o1 < W2Sd) ? brel[h*W2Sd + o1] : 0.f;
            sRelh[g*RELB + o0]     = __float2bfloat16(c0 + br0);
            sRelh[g*RELB + o1]     = __float2bfloat16(c1 + br1);
            sRelh[(g+8)*RELB + o0] = __float2bfloat16(c2 + br0);
            sRelh[(g+8)*RELB + o1] = __float2bfloat16(c3 + br1);
        }
    }

    // ---- pack scaled Q as bf16x2 ----
    {
        int q = t >> 4, c2 = t & 15;
        int qy = q >> 2, qx = q & 3;
        int tokq = b*HW + (ty0+qy)*Wd + tx0+qx;
        float2 v = *(const float2*)(g_Q + (size_t)tokq*Cd + h*HDd + c2*2);
        v.x *= scale; v.y *= scale;
        ((__nv_bfloat162*)sQ)[q*PKW + c2] = __float22bfloat162_rn(v);
    }

    // ---- K load: pos-major bf16x2, zero-padded ----
    for (int i = t; i < EXTP*16; i += 256) {
        int pos = i >> 4, c2 = i & 15;
        float2 v = make_float2(0.f, 0.f);
        if (pos < EXT2) {
            int wy = pos / EXT, wx = pos - (pos/EXT)*EXT;
            int ky = wy0 + wy, kx = wx0 + wx;
            if (ky >= 0 && ky < Hh && kx >= 0 && kx < Wd)
                v = *(const float2*)(g_K + (size_t)(b*HW + ky*Wd + kx)*Cd + h*HDd + c2*2);
        }
        ((__nv_bfloat162*)sBig)[pos*PKW + c2] = __float22bfloat162_rn(v);
    }
    __syncthreads();

    // ---- score MMA: sS[16][336] = Qs x Kext^T (bf16) ----
    {
        unsigned a[2][4];
        #pragma unroll
        for (int ks = 0; ks < 2; ks++) {
            a[ks][0] = sQ[g*PKW + ks*8 + t4];
            a[ks][1] = sQ[(g+8)*PKW + ks*8 + t4];
            a[ks][2] = sQ[g*PKW + ks*8 + t4 + 4];
            a[ks][3] = sQ[(g+8)*PKW + ks*8 + t4 + 4];
        }
        for (int nt = warp; nt < EXTP/8; nt += 8) {
            int n0 = nt*8;
            float c0 = 0.f, c1 = 0.f, c2v = 0.f, c3 = 0.f;
            #pragma unroll
            for (int ks = 0; ks < 2; ks++) {
                unsigned b0 = sBig[(n0+g)*PKW + ks*8 + t4];
                unsigned b1 = sBig[(n0+g)*PKW + ks*8 + t4 + 4];
                mma_bf16(c0, c1, c2v, c3,
                         a[ks][0], a[ks][1], a[ks][2], a[ks][3], b0, b1);
            }
            sS[g*SSP + n0 + 2*t4]         = c0;
            sS[g*SSP + n0 + 2*t4 + 1]     = c1;
            sS[(g+8)*SSP + n0 + 2*t4]     = c2v;
            sS[(g+8)*SSP + n0 + 2*t4 + 1] = c3;
        }
    }
    __syncthreads();

    // ---- K dead: zero whole union region (P + V) ----
    for (int i = t; i < NBIG; i += 256) sBig[i] = 0;
    __syncthreads();

    // ---- masked softmax (scatter bf16 probs into sP) + V load ----
    {
        int q = t >> 4, lo = t & 15;
        int qy = q >> 2, qx = q & 3;
        float mx = NEGINF;
        for (int o = lo; o < W2Sd; o += 16) {
            int oy = o / WSd, ox = o - (o/WSd)*WSd;
            int ky = ty0 + qy + oy - MDd, kx = tx0 + qx + ox - MDd;
            if (ky >= 0 && ky < Hh && kx >= 0 && kx < Wd) {
                int pos = (qy + oy)*EXT + (qx + ox);
                float s = sS[q*SSP + pos] + __bfloat162float(sRelh[q*RELB + o]);
                mx = fmaxf(mx, s);
            }
        }
        #pragma unroll
        for (int d = 8; d > 0; d >>= 1)
            mx = fmaxf(mx, __shfl_xor_sync(0xffffffffu, mx, d));
        float sum = 0.f;
        __nv_bfloat16* pb = (__nv_bfloat16*)sP;
        for (int o = lo; o < W2Sd; o += 16) {
            int oy = o / WSd, ox = o - (o/WSd)*WSd;
            int ky = ty0 + qy + oy - MDd, kx = tx0 + qx + ox - MDd;
            if (ky >= 0 && ky < Hh && kx >= 0 && kx < Wd) {
                int pos = (qy + oy)*EXT + (qx + ox);
                float s = sS[q*SSP + pos] + __bfloat162float(sRelh[q*RELB + o]);
                float e = __expf(s - mx);
                pb[q*(2*PVW) + pos] = __float2bfloat16(e);
                sum += e;
            }
        }
        #pragma unroll
        for (int d = 8; d > 0; d >>= 1)
            sum += __shfl_xor_sync(0xffffffffu, sum, d);
        if (lo == 0) sInv[q] = 1.f / sum;
    }
    // V load: channel-major bf16 [32 ch][344 slots] (region pre-zeroed)
    {
        __nv_bfloat16* vb = (__nv_bfloat16*)sV;
        for (int i = t; i < EXT2*16; i += 256) {
            int pos = i >> 4, c2 = i & 15;
            int wy = pos / EXT, wx = pos - (pos/EXT)*EXT;
            int ky = wy0 + wy, kx = wx0 + wx;
            if (ky >= 0 && ky < Hh && kx >= 0 && kx < Wd) {
                float2 v = *(const float2*)(g_V + (size_t)(b*HW + ky*Wd + kx)*Cd + h*HDd + c2*2);
                vb[(2*c2    )*(2*PVW) + pos] = __float2bfloat16(v.x);
                vb[(2*c2 + 1)*(2*PVW) + pos] = __float2bfloat16(v.y);
            }
        }
    }
    __syncthreads();

    // ---- PV MMA: O[16][32] = P x Vext ; warp = (khalf, ntile) ----
    {
        int khalf = warp >> 2, ntile = warp & 3;
        int n0 = ntile*8;
        int ks0 = khalf ? 11 : 0, ks1 = khalf ? 21 : 11;
        float c0 = 0.f, c1 = 0.f, c2v = 0.f, c3 = 0.f;
        for (int ks = ks0; ks < ks1; ks++) {
            int kw = ks*8;
            unsigned a0 = sP[g*PVW + kw + t4];
            unsigned a1 = sP[(g+8)*PVW + kw + t4];
            unsigned a2 = sP[g*PVW + kw + t4 + 4];
            unsigned a3 = sP[(g+8)*PVW + kw + t4 + 4];
            unsigned b0 = sV[(n0+g)*PVW + kw + t4];
            unsigned b1 = sV[(n0+g)*PVW + kw + t4 + 4];
            mma_bf16(c0, c1, c2v, c3, a0, a1, a2, a3, b0, b1);
        }
        if (khalf == 1) {
            sRed[ntile*128 + g*8 + 2*t4]           = c0;
            sRed[ntile*128 + g*8 + 2*t4 + 1]       = c1;
            sRed[ntile*128 + (g+8)*8 + 2*t4]       = c2v;
            sRed[ntile*128 + (g+8)*8 + 2*t4 + 1]   = c3;
        }
        __syncthreads();
        if (khalf == 0) {
            c0  += sRed[ntile*128 + g*8 + 2*t4];
            c1  += sRed[ntile*128 + g*8 + 2*t4 + 1];
            c2v += sRed[ntile*128 + (g+8)*8 + 2*t4];
            c3  += sRed[ntile*128 + (g+8)*8 + 2*t4 + 1];
            int q0 = g, q1 = g + 8;
            int tok0 = b*HW + (ty0 + (q0 >> 2))*Wd + tx0 + (q0 & 3);
            int tok1 = b*HW + (ty0 + (q1 >> 2))*Wd + tx0 + (q1 & 3);
            float i0 = sInv[q0], i1 = sInv[q1];
            float* o0 = g_att + (size_t)tok0*Cd + h*HDd + n0 + 2*t4;
            float* o1 = g_att + (size_t)tok1*Cd + h*HDd + n0 + 2*t4;
            o0[0] = c0  * i0; o0[1] = c1 * i0;
            o1[0] = c2v * i1; o1[1] = c3 * i1;
        }
    }
}

// ---------------- GroupNorm stats per (b, group) ----------------
__global__ void gn_stats_kernel() {
    int bg = blockIdx.x;
    int b = bg / GNg, g = bg % GNg;
    int tid = threadIdx.x;
    float sm = 0.f, sq = 0.f;
    for (int i = tid; i < HW*32; i += 256) {
        int ch  = g*32 + (i & 31);
        int pos = i >> 5;
        float v = g_h1[(size_t)(b*HW + pos)*HIDd + ch];
        sm += v; sq += v*v;
    }
    #pragma unroll
    for (int d = 16; d > 0; d >>= 1) {
        sm += __shfl_xor_sync(0xffffffffu, sm, d);
        sq += __shfl_xor_sync(0xffffffffu, sq, d);
    }
    __shared__ float s1[8], s2[8];
    int warp = tid >> 5, lane = tid & 31;
    if (lane == 0) { s1[warp] = sm; s2[warp] = sq; }
    __syncthreads();
    if (tid == 0) {
        float ss = 0.f, qq = 0.f;
        #pragma unroll
        for (int i = 0; i < 8; i++) { ss += s1[i]; qq += s2[i]; }
        float cnt = (float)(HW*32);
        float mu  = ss / cnt;
        float var = qq / cnt - mu*mu;
        g_gnm[bg*2]   = mu;
        g_gnm[bg*2+1] = rsqrtf(var + EPSf);
    }
}

// ---------------- fused GN + GELU + 5x5 depthwise conv ----------------
__global__ void dwconv_fused_kernel(const float* __restrict__ gg,
                                    const float* __restrict__ gb,
                                    const float* __restrict__ Wdw) {
    __shared__ float sT[144][68];

    int tileid = blockIdx.x;
    int cg = blockIdx.y, b = blockIdx.z;
    int ty0 = (tileid / 5) * 8, tx0 = (tileid % 5) * 8;
    int tid = threadIdx.x;
    int ch  = tid & 63;
    int chg = cg*64 + ch;

    float gamma = gg[chg], beta = gb[chg];
    int grp = chg >> 5;
    float mu = g_gnm[(b*GNg + grp)*2];
    float rs = g_gnm[(b*GNg + grp)*2 + 1];

    float wreg[25];
    #pragma unroll
    for (int i = 0; i < 25; i++) wreg[i] = Wdw[chg*25 + i];

    for (int i = tid; i < 144*64; i += 256) {
        int pos = i >> 6;
        int wy = pos / 12, wx = pos - (pos/12)*12;
        int y = ty0 + wy - 2, x = tx0 + wx - 2;
        float v = 0.f;
        if (y >= 0 && y < Hh && x >= 0 && x < Wd) {
            float hv = g_h1[(size_t)(b*HW + y*Wd + x)*HIDd + chg];
            hv = (hv - mu) * rs * gamma + beta;
            v = 0.5f * hv * (1.f + erff(hv * 0.70710678118654752f));
        }
        sT[pos][ch] = v;
    }
    __syncthreads();

    int pg = tid >> 6;
    #pragma unroll
    for (int p = 0; p < 16; p++) {
        int po = pg*16 + p;
        int y = po >> 3, x = po & 7;
        float acc = 0.f;
        #pragma unroll
        for (int dy = 0; dy < 5; dy++)
            #pragma unroll
            for (int dx = 0; dx < 5; dx++)
                acc += wreg[dy*5+dx] * sT[(y+dy)*12 + (x+dx)][ch];
        g_cv[(size_t)(b*HW + (ty0+y)*Wd + (tx0+x))*HIDd + chg] = acc;
    }
}

// ---------------- launch ----------------
extern "C" void kernel_launch(void* const* d_in, const int* in_sizes, int n_in,
                              void* d_out, int out_size) {
    const float* img   = (const float*)d_in[0];
    const float* imw   = (const float*)d_in[1];
    const float* msk   = (const float*)d_in[2];
    const float* ln1g  = (const float*)d_in[3];
    const float* ln1b  = (const float*)d_in[4];
    const float* ln2g  = (const float*)d_in[5];
    const float* ln2b  = (const float*)d_in[6];
    const float* Wq    = (const float*)d_in[7];
    const float* bq    = (const float*)d_in[8];
    const float* Wk    = (const float*)d_in[9];
    const float* bk    = (const float*)d_in[10];
    const float* Wv    = (const float*)d_in[11];
    const float* bv    = (const float*)d_in[12];
    const float* Wrel  = (const float*)d_in[13];
    const float* brel  = (const float*)d_in[14];
    const float* Wproj = (const float*)d_in[15];
    const float* bproj = (const float*)d_in[16];
    const float* W1    = (const float*)d_in[17];
    const float* bW1   = (const float*)d_in[18];
    const float* gng   = (const float*)d_in[19];
    const float* gnb   = (const float*)d_in[20];
    const float* Wdw   = (const float*)d_in[21];
    const float* W2    = (const float*)d_in[22];
    const float* bW2   = (const float*)d_in[23];
    float* out = (float*)d_out;

    float *qln, *kln, *vln, *Q, *K, *V, *att, *x1, *ln2, *h1, *cv;
    cudaGetSymbolAddress((void**)&qln, g_qln);
    cudaGetSymbolAddress((void**)&kln, g_kln);
    cudaGetSymbolAddress((void**)&vln, g_vln);
    cudaGetSymbolAddress((void**)&Q,   g_Q);
    cudaGetSymbolAddress((void**)&K,   g_K);
    cudaGetSymbolAddress((void**)&V,   g_V);
    cudaGetSymbolAddress((void**)&att, g_att);
    cudaGetSymbolAddress((void**)&x1,  g_x1);
    cudaGetSymbolAddress((void**)&ln2, g_ln2);
    cudaGetSymbolAddress((void**)&h1,  g_h1);
    cudaGetSymbolAddress((void**)&cv,  g_cv);

    int smem128 = (2*128*KP + 2*BN*KP) * sizeof(float);
    cudaFuncSetAttribute(mma_gemm_kernel<128>,
                         cudaFuncAttributeMaxDynamicSharedMemorySize, smem128);
    cudaFuncSetAttribute(mma_qkv_kernel,
                         cudaFuncAttributeMaxDynamicSharedMemorySize, smem128);

    // 1. LayerNorms
    ln3_kernel<<<TOK, 256>>>(img, imw, msk, ln1g, ln1b);

    // 2. QKV projections
    QKVArgs qa;
    qa.A[0] = qln; qa.A[1] = kln; qa.A[2] = vln;
    qa.W[0] = Wq;  qa.W[1] = Wk;  qa.W[2] = Wv;
    qa.bias[0] = bq; qa.bias[1] = bk; qa.bias[2] = bv;
    qa.C[0] = Q; qa.C[1] = K; qa.C[2] = V;
    mma_qkv_kernel<<<dim3(Cd/BN, TOK/128, 3), 256, smem128>>>(qa);

    // 3. tensor-core attention v3 (65.9KB smem -> 3 blocks/SM)
    int attn_smem = (16*PKW + NBIG + 16*SSP + 512 + 16) * 4 + 16*RELB*2;
    cudaFuncSetAttribute(attn_tile_kernel,
                         cudaFuncAttributeMaxDynamicSharedMemorySize, attn_smem);
    attn_tile_kernel<<<dim3((Hh/QT)*(Wd/QT), NHd, Bz), 256, attn_smem>>>(Wrel, brel);

    // 4. output projection + fused residual -> x1
    mma_gemm_kernel<128><<<dim3(Cd/BN, TOK/128), 256, smem128>>>(att, Wproj, bproj, x1,
                                                                 Cd, Cd, 1, img);

    // 5. MLP branch
    ln_tok_kernel<<<TOK, 256>>>(ln2g, ln2b);
    mma_gemm_kernel<128><<<dim3(HIDd/BN, TOK/128), 256, smem128>>>(ln2, W1, bW1, h1,
                                                                   HIDd, Cd, 0, nullptr);
    gn_stats_kernel<<<Bz*GNg, 256>>>();
    dwconv_fused_kernel<<<dim3(25, HIDd/64, Bz), 256>>>(gng, gnb, Wdw);

    // 6. W2 + fused final residual + transpose to BCHW
    mma_gemm_kernel<128><<<dim3(Cd/BN, TOK/128), 256, smem128>>>(cv, W2, bW2, out,
                                                                 Cd, HIDd, 2, x1);
}

// round 17
// speedup vs baseline: 1.1327x; 1.0764x over previous
#include <cuda_runtime.h>
#include <cuda_bf16.h>
#include <math.h>

#define Bz   2
#define Cd   256
#define Hh   40
#define Wd   40
#define HW   1600
#define TOK  3200
#define NHd  8
#define HDd  32
#define WSd  15
#define W2Sd 225
#define MDd  7
#define HIDd 1024
#define GNg  32
#define EPSf 1e-5f
#define NEGINF -1e38f

// attention MMA tiling
#define QT    4
#define EXT   18
#define EXT2  (EXT*EXT)    // 324
#define EXTP  336          // padded to 21 k16 steps
#define PKW   20           // K row stride (u32 words), [pos][ch-pairs]
#define PVW   172          // P/V row stride (u32 words)
#define SSB   344          // bf16 score row stride (elements)
#define RELB  240          // bf16 rel row stride
#define NBIG  8256         // union region: max(336*20, 16*172 + 32*172)

// GEMM tiling
#define BN 64
#define BK 32
#define KP 36

// ---------------- scratch ----------------
__device__ float g_qln[TOK*Cd];
__device__ float g_kln[TOK*Cd];
__device__ float g_vln[TOK*Cd];
__device__ float g_Q[TOK*Cd];
__device__ float g_K[TOK*Cd];
__device__ float g_V[TOK*Cd];
__device__ float g_att[TOK*Cd];
__device__ float g_x1[TOK*Cd];
__device__ float g_ln2[TOK*Cd];
__device__ float g_h1[TOK*HIDd];
__device__ float g_cv[TOK*HIDd];
__device__ float g_gnm[Bz*GNg*2];

// ---------------- block mean/var helper (256 threads) ----------------
__device__ __forceinline__ void block_meanvar(float v, float* sbuf,
                                              float& mu, float& rstd) {
    float s = v, q = v*v;
    #pragma unroll
    for (int d = 16; d > 0; d >>= 1) {
        s += __shfl_xor_sync(0xffffffffu, s, d);
        q += __shfl_xor_sync(0xffffffffu, q, d);
    }
    int warp = threadIdx.x >> 5, lane = threadIdx.x & 31;
    if (lane == 0) { sbuf[warp] = s; sbuf[8 + warp] = q; }
    __syncthreads();
    if (warp == 0) {
        float ss = (lane < 8) ? sbuf[lane] : 0.f;
        float qq = (lane < 8) ? sbuf[8 + lane] : 0.f;
        #pragma unroll
        for (int d = 4; d > 0; d >>= 1) {
            ss += __shfl_xor_sync(0xffffffffu, ss, d);
            qq += __shfl_xor_sync(0xffffffffu, qq, d);
        }
        if (lane == 0) {
            float m = ss * (1.0f/Cd);
            float var = qq * (1.0f/Cd) - m*m;
            sbuf[16] = m;
            sbuf[17] = rsqrtf(var + EPSf);
        }
    }
    __syncthreads();
    mu = sbuf[16]; rstd = sbuf[17];
}

// ---------------- fused LN of img / img_warp / img_warp+mask ----------------
__global__ void ln3_kernel(const float* __restrict__ img,
                           const float* __restrict__ imw,
                           const float* __restrict__ msk,
                           const float* __restrict__ g1,
                           const float* __restrict__ b1) {
    int tok = blockIdx.x;
    int c   = threadIdx.x;
    int b   = tok / HW, pos = tok % HW;
    int off = (b*Cd + c)*HW + pos;

    float x0 = img[off];
    float x1 = imw[off];
    float x2 = x1 + msk[off];
    float gg = g1[c], bb = b1[c];

    __shared__ float sbuf[18];
    float mu, rs;

    block_meanvar(x0, sbuf, mu, rs);
    g_qln[tok*Cd + c] = (x0 - mu) * rs * gg + bb;
    __syncthreads();
    block_meanvar(x1, sbuf, mu, rs);
    g_kln[tok*Cd + c] = (x1 - mu) * rs * gg + bb;
    __syncthreads();
    block_meanvar(x2, sbuf, mu, rs);
    g_vln[tok*Cd + c] = (x2 - mu) * rs * gg + bb;
}

__global__ void ln_tok_kernel(const float* __restrict__ g1,
                              const float* __restrict__ b1) {
    int tok = blockIdx.x;
    int c   = threadIdx.x;
    float v = g_x1[tok*Cd + c];
    __shared__ float sbuf[18];
    float mu, rs;
    block_meanvar(v, sbuf, mu, rs);
    g_ln2[tok*Cd + c] = (v - mu) * rs * g1[c] + b1[c];
}

// ---------------- MMA helpers ----------------
__device__ __forceinline__ unsigned f2tf32(float x) {
    unsigned r;
    asm("cvt.rna.tf32.f32 %0, %1;" : "=r"(r) : "f"(x));
    return r;
}
__device__ __forceinline__ void mma_tf32(float& c0, float& c1, float& c2, float& c3,
                                         unsigned a0, unsigned a1, unsigned a2, unsigned a3,
                                         unsigned b0, unsigned b1) {
    asm volatile(
        "mma.sync.aligned.m16n8k8.row.col.f32.tf32.tf32.f32 "
        "{%0,%1,%2,%3}, {%4,%5,%6,%7}, {%8,%9}, {%0,%1,%2,%3};"
        : "+f"(c0), "+f"(c1), "+f"(c2), "+f"(c3)
        : "r"(a0), "r"(a1), "r"(a2), "r"(a3), "r"(b0), "r"(b1));
}
__device__ __forceinline__ void mma_bf16(float& c0, float& c1, float& c2, float& c3,
                                         unsigned a0, unsigned a1, unsigned a2, unsigned a3,
                                         unsigned b0, unsigned b1) {
    asm volatile(
        "mma.sync.aligned.m16n8k16.row.col.f32.bf16.bf16.f32 "
        "{%0,%1,%2,%3}, {%4,%5,%6,%7}, {%8,%9}, {%0,%1,%2,%3};"
        : "+f"(c0), "+f"(c1), "+f"(c2), "+f"(c3)
        : "r"(a0), "r"(a1), "r"(a2), "r"(a3), "r"(b0), "r"(b1));
}
__device__ __forceinline__ void cp_async16(unsigned dst, const void* src) {
    asm volatile("cp.async.cg.shared.global [%0], [%1], 16;\n"
                 :: "r"(dst), "l"(src));
}
__device__ __forceinline__ void cp_commit() {
    asm volatile("cp.async.commit_group;\n");
}

// ---------------- tf32 GEMM, cp.async double buffered ----------
template<int BMT>
__device__ __forceinline__ void mma_body(const float* __restrict__ A, int lda,
                                         const float* __restrict__ Wt,
                                         const float* __restrict__ bias,
                                         float* __restrict__ C,
                                         int N, int K, int m0, int n0,
                                         int mode, const float* __restrict__ res) {
    constexpr int MT = BMT / 64;
    extern __shared__ float smem[];
    float* As = smem;
    float* Ws = smem + 2*BMT*KP;

    int tid  = threadIdx.x;
    int lane = tid & 31, warp = tid >> 5;
    int wm = (warp >> 1) * (16*MT), wn = (warp & 1) * 32;
    int g = lane >> 2, t4 = lane & 3;

    float acc[MT][4][4] = {};
    int steps = K / BK;

    unsigned sA = (unsigned)__cvta_generic_to_shared(As);
    unsigned sW = (unsigned)__cvta_generic_to_shared(Ws);

    auto load_stage = [&](int kc, int s) {
        int k0 = kc * BK;
        #pragma unroll
        for (int it = 0; it < BMT/32; it++) {
            int idx = tid + it*256;
            int row = idx >> 3, ch = (idx & 7) * 4;
            cp_async16(sA + (unsigned)(((s*BMT + row)*KP + ch) * 4),
                       &A[(size_t)(m0+row)*lda + k0 + ch]);
        }
        #pragma unroll
        for (int it = 0; it < 2; it++) {
            int idx = tid + it*256;
            int row = idx >> 3, ch = (idx & 7) * 4;
            cp_async16(sW + (unsigned)(((s*BN + row)*KP + ch) * 4),
                       &Wt[(size_t)(n0+row)*K + k0 + ch]);
        }
        cp_commit();
    };

    load_stage(0, 0);

    for (int kc = 0; kc < steps; kc++) {
        int s = kc & 1;
        if (kc + 1 < steps) {
            load_stage(kc + 1, (kc + 1) & 1);
            asm volatile("cp.async.wait_group 1;\n");
        } else {
            asm volatile("cp.async.wait_group 0;\n");
        }
        __syncthreads();

        float* Ab = As + s*BMT*KP;
        float* Wb = Ws + s*BN*KP;
        #pragma unroll
        for (int ks = 0; ks < BK; ks += 8) {
            unsigned a[MT][4], bf[4][2];
            #pragma unroll
            for (int mt = 0; mt < MT; mt++) {
                int rb = wm + mt*16;
                a[mt][0] = f2tf32(Ab[(rb + g    )*KP + ks + t4    ]);
                a[mt][1] = f2tf32(Ab[(rb + g + 8)*KP + ks + t4    ]);
                a[mt][2] = f2tf32(Ab[(rb + g    )*KP + ks + t4 + 4]);
                a[mt][3] = f2tf32(Ab[(rb + g + 8)*KP + ks + t4 + 4]);
            }
            #pragma unroll
            for (int nt = 0; nt < 4; nt++) {
                int nb = wn + nt*8 + g;
                bf[nt][0] = f2tf32(Wb[nb*KP + ks + t4    ]);
                bf[nt][1] = f2tf32(Wb[nb*KP + ks + t4 + 4]);
            }
            #pragma unroll
            for (int mt = 0; mt < MT; mt++)
                #pragma unroll
                for (int nt = 0; nt < 4; nt++)
                    mma_tf32(acc[mt][nt][0], acc[mt][nt][1],
                             acc[mt][nt][2], acc[mt][nt][3],
                             a[mt][0], a[mt][1], a[mt][2], a[mt][3],
                             bf[nt][0], bf[nt][1]);
        }
        __syncthreads();
    }

    #pragma unroll
    for (int mt = 0; mt < MT; mt++) {
        #pragma unroll
        for (int nt = 0; nt < 4; nt++) {
            #pragma unroll
            for (int i = 0; i < 4; i++) {
                int mrow = m0 + wm + mt*16 + g + ((i >= 2) ? 8 : 0);
                int ncol = n0 + wn + nt*8 + 2*t4 + (i & 1);
                float v = acc[mt][nt][i] + bias[ncol];
                if (mode == 0) {
                    C[(size_t)mrow*N + ncol] = v;
                } else if (mode == 1) {
                    int b = mrow / HW, pos = mrow % HW;
                    C[(size_t)mrow*N + ncol] =
                        v + res[(size_t)(b*Cd + ncol)*HW + pos];
                } else {
                    int b = mrow / HW, pos = mrow % HW;
                    C[(size_t)(b*Cd + ncol)*HW + pos] =
                        v + res[(size_t)mrow*N + ncol];
                }
            }
        }
    }
}

template<int BMT>
__global__ void mma_gemm_kernel(const float* __restrict__ A,
                                const float* __restrict__ Wt,
                                const float* __restrict__ bias,
                                float* __restrict__ C,
                                int N, int K, int mode,
                                const float* __restrict__ res) {
    mma_body<BMT>(A, K, Wt, bias, C, N, K, blockIdx.y*BMT, blockIdx.x*BN, mode, res);
}

struct QKVArgs {
    const float* A[3];
    const float* W[3];
    const float* bias[3];
    float* C[3];
};
__global__ void mma_qkv_kernel(QKVArgs args) {
    int z = blockIdx.z;
    mma_body<128>(args.A[z], Cd, args.W[z], args.bias[z], args.C[z],
                  Cd, Cd, blockIdx.y*128, blockIdx.x*BN, 0, nullptr);
}

// ---------------- tensor-core local attention v4 (bf16 scores) ------------
// layout (words): sQ[0,320) | sBig[320,8576) | sSb(bf16, 2752w) |
//                 sRed[512w] | sRelh(bf16, 1920w) | sInv[16w]
__global__ void attn_tile_kernel(const float* __restrict__ Wrel,
                                 const float* __restrict__ brel) {
    extern __shared__ float smem[];
    unsigned* sQ   = (unsigned*)smem;
    unsigned* sBig = sQ + 16*PKW;
    __nv_bfloat16* sSb = (__nv_bfloat16*)(sBig + NBIG);      // [16][SSB]
    float*    sRed = (float*)(sSb + 16*SSB);
    __nv_bfloat16* sRelh = (__nv_bfloat16*)(sRed + 512);
    float*    sInv = (float*)(sRelh + 16*RELB);

    unsigned* sP = sBig;              // [16 q][PVW]   (after score phase)
    unsigned* sV = sBig + 16*PVW;     // [32 ch][PVW]

    int tile = blockIdx.x;
    int h = blockIdx.y, b = blockIdx.z;
    int ty0 = (tile / (Wd/QT)) * QT;
    int tx0 = (tile % (Wd/QT)) * QT;
    int t = threadIdx.x;
    int lane = t & 31, warp = t >> 5;
    int g = lane >> 2, t4 = lane & 3;

    const float scale = 0.17677669529663687f;
    int wy0 = ty0 - MDd, wx0 = tx0 - MDd;

    // ---- rel MMA prologue: sRelh[16q][225o] = Qtile x Wrel[h]^T + brel ----
    {
        unsigned aq[4][4];
        int q0 = g, q1 = g + 8;
        int tk0 = b*HW + (ty0 + (q0 >> 2))*Wd + tx0 + (q0 & 3);
        int tk1 = b*HW + (ty0 + (q1 >> 2))*Wd + tx0 + (q1 & 3);
        const float* Q0 = g_Q + (size_t)tk0*Cd + h*HDd;
        const float* Q1 = g_Q + (size_t)tk1*Cd + h*HDd;
        #pragma unroll
        for (int ks = 0; ks < 4; ks++) {
            aq[ks][0] = f2tf32(Q0[ks*8 + t4]);
            aq[ks][1] = f2tf32(Q1[ks*8 + t4]);
            aq[ks][2] = f2tf32(Q0[ks*8 + t4 + 4]);
            aq[ks][3] = f2tf32(Q1[ks*8 + t4 + 4]);
        }
        const float* Wh = Wrel + (size_t)h*W2Sd*HDd;
        for (int nt = warp; nt < 29; nt += 8) {
            int n0 = nt*8;
            int o = n0 + g;
            float c0 = 0.f, c1 = 0.f, c2 = 0.f, c3 = 0.f;
            #pragma unroll
            for (int ks = 0; ks < 4; ks++) {
                float w0 = 0.f, w1 = 0.f;
                if (o < W2Sd) {
                    w0 = Wh[o*HDd + ks*8 + t4];
                    w1 = Wh[o*HDd + ks*8 + t4 + 4];
                }
                mma_tf32(c0, c1, c2, c3,
                         aq[ks][0], aq[ks][1], aq[ks][2], aq[ks][3],
                         f2tf32(w0), f2tf32(w1));
            }
            int o0 = n0 + 2*t4, o1 = o0 + 1;
            float br0 = (o0 < W2Sd) ? brel[h*W2Sd + o0] : 0.f;
            float br1 = (o1 < W2Sd) ? brel[h*W2Sd + o1] : 0.f;
            sRelh[g*RELB + o0]     = __float2bfloat16(c0 + br0);
            sRelh[g*RELB + o1]     = __float2bfloat16(c1 + br1);
            sRelh[(g+8)*RELB + o0] = __float2bfloat16(c2 + br0);
            sRelh[(g+8)*RELB + o1] = __float2bfloat16(c3 + br1);
        }
    }

    // ---- pack scaled Q as bf16x2 ----
    {
        int q = t >> 4, c2 = t & 15;
        int qy = q >> 2, qx = q & 3;
        int tokq = b*HW + (ty0+qy)*Wd + tx0+qx;
        float2 v = *(const float2*)(g_Q + (size_t)tokq*Cd + h*HDd + c2*2);
        v.x *= scale; v.y *= scale;
        ((__nv_bfloat162*)sQ)[q*PKW + c2] = __float22bfloat162_rn(v);
    }

    // ---- K load: pos-major bf16x2, zero-padded ----
    for (int i = t; i < EXTP*16; i += 256) {
        int pos = i >> 4, c2 = i & 15;
        float2 v = make_float2(0.f, 0.f);
        if (pos < EXT2) {
            int wy = pos / EXT, wx = pos - (pos/EXT)*EXT;
            int ky = wy0 + wy, kx = wx0 + wx;
            if (ky >= 0 && ky < Hh && kx >= 0 && kx < Wd)
                v = *(const float2*)(g_K + (size_t)(b*HW + ky*Wd + kx)*Cd + h*HDd + c2*2);
        }
        ((__nv_bfloat162*)sBig)[pos*PKW + c2] = __float22bfloat162_rn(v);
    }
    __syncthreads();

    // ---- score MMA: sSb[16][336] = Qs x Kext^T (bf16, bf16 out) ----
    {
        unsigned a[2][4];
        #pragma unroll
        for (int ks = 0; ks < 2; ks++) {
            a[ks][0] = sQ[g*PKW + ks*8 + t4];
            a[ks][1] = sQ[(g+8)*PKW + ks*8 + t4];
            a[ks][2] = sQ[g*PKW + ks*8 + t4 + 4];
            a[ks][3] = sQ[(g+8)*PKW + ks*8 + t4 + 4];
        }
        __nv_bfloat162* sS2 = (__nv_bfloat162*)sSb;
        for (int nt = warp; nt < EXTP/8; nt += 8) {
            int n0 = nt*8;
            float c0 = 0.f, c1 = 0.f, c2v = 0.f, c3 = 0.f;
            #pragma unroll
            for (int ks = 0; ks < 2; ks++) {
                unsigned b0 = sBig[(n0+g)*PKW + ks*8 + t4];
                unsigned b1 = sBig[(n0+g)*PKW + ks*8 + t4 + 4];
                mma_bf16(c0, c1, c2v, c3,
                         a[ks][0], a[ks][1], a[ks][2], a[ks][3], b0, b1);
            }
            sS2[(g*SSB + n0)/2 + t4]     = __float22bfloat162_rn(make_float2(c0, c1));
            sS2[((g+8)*SSB + n0)/2 + t4] = __float22bfloat162_rn(make_float2(c2v, c3));
        }
    }
    __syncthreads();

    // ---- K dead: zero whole union region (P + V) ----
    for (int i = t; i < NBIG; i += 256) sBig[i] = 0;
    __syncthreads();

    // ---- masked softmax (scatter bf16 probs into sP) + V load ----
    {
        int q = t >> 4, lo = t & 15;
        int qy = q >> 2, qx = q & 3;
        float mx = NEGINF;
        for (int o = lo; o < W2Sd; o += 16) {
            int oy = o / WSd, ox = o - (o/WSd)*WSd;
            int ky = ty0 + qy + oy - MDd, kx = tx0 + qx + ox - MDd;
            if (ky >= 0 && ky < Hh && kx >= 0 && kx < Wd) {
                int pos = (qy + oy)*EXT + (qx + ox);
                float s = __bfloat162float(sSb[q*SSB + pos])
                        + __bfloat162float(sRelh[q*RELB + o]);
                mx = fmaxf(mx, s);
            }
        }
        #pragma unroll
        for (int d = 8; d > 0; d >>= 1)
            mx = fmaxf(mx, __shfl_xor_sync(0xffffffffu, mx, d));
        float sum = 0.f;
        __nv_bfloat16* pb = (__nv_bfloat16*)sP;
        for (int o = lo; o < W2Sd; o += 16) {
            int oy = o / WSd, ox = o - (o/WSd)*WSd;
            int ky = ty0 + qy + oy - MDd, kx = tx0 + qx + ox - MDd;
            if (ky >= 0 && ky < Hh && kx >= 0 && kx < Wd) {
                int pos = (qy + oy)*EXT + (qx + ox);
                float s = __bfloat162float(sSb[q*SSB + pos])
                        + __bfloat162float(sRelh[q*RELB + o]);
                float e = __expf(s - mx);
                pb[q*(2*PVW) + pos] = __float2bfloat16(e);
                sum += e;
            }
        }
        #pragma unroll
        for (int d = 8; d > 0; d >>= 1)
            sum += __shfl_xor_sync(0xffffffffu, sum, d);
        if (lo == 0) sInv[q] = 1.f / sum;
    }
    // V load: channel-major bf16 [32 ch][344 slots] (region pre-zeroed)
    {
        __nv_bfloat16* vb = (__nv_bfloat16*)sV;
        for (int i = t; i < EXT2*16; i += 256) {
            int pos = i >> 4, c2 = i & 15;
            int wy = pos / EXT, wx = pos - (pos/EXT)*EXT;
            int ky = wy0 + wy, kx = wx0 + wx;
            if (ky >= 0 && ky < Hh && kx >= 0 && kx < Wd) {
                float2 v = *(const float2*)(g_V + (size_t)(b*HW + ky*Wd + kx)*Cd + h*HDd + c2*2);
                vb[(2*c2    )*(2*PVW) + pos] = __float2bfloat16(v.x);
                vb[(2*c2 + 1)*(2*PVW) + pos] = __float2bfloat16(v.y);
            }
        }
    }
    __syncthreads();

    // ---- PV MMA: O[16][32] = P x Vext ; warp = (khalf, ntile) ----
    {
        int khalf = warp >> 2, ntile = warp & 3;
        int n0 = ntile*8;
        int ks0 = khalf ? 11 : 0, ks1 = khalf ? 21 : 11;
        float c0 = 0.f, c1 = 0.f, c2v = 0.f, c3 = 0.f;
        for (int ks = ks0; ks < ks1; ks++) {
            int kw = ks*8;
            unsigned a0 = sP[g*PVW + kw + t4];
            unsigned a1 = sP[(g+8)*PVW + kw + t4];
            unsigned a2 = sP[g*PVW + kw + t4 + 4];
            unsigned a3 = sP[(g+8)*PVW + kw + t4 + 4];
            unsigned b0 = sV[(n0+g)*PVW + kw + t4];
            unsigned b1 = sV[(n0+g)*PVW + kw + t4 + 4];
            mma_bf16(c0, c1, c2v, c3, a0, a1, a2, a3, b0, b1);
        }
        if (khalf == 1) {
            sRed[ntile*128 + g*8 + 2*t4]           = c0;
            sRed[ntile*128 + g*8 + 2*t4 + 1]       = c1;
            sRed[ntile*128 + (g+8)*8 + 2*t4]       = c2v;
            sRed[ntile*128 + (g+8)*8 + 2*t4 + 1]   = c3;
        }
        __syncthreads();
        if (khalf == 0) {
            c0  += sRed[ntile*128 + g*8 + 2*t4];
            c1  += sRed[ntile*128 + g*8 + 2*t4 + 1];
            c2v += sRed[ntile*128 + (g+8)*8 + 2*t4];
            c3  += sRed[ntile*128 + (g+8)*8 + 2*t4 + 1];
            int q0 = g, q1 = g + 8;
            int tok0 = b*HW + (ty0 + (q0 >> 2))*Wd + tx0 + (q0 & 3);
            int tok1 = b*HW + (ty0 + (q1 >> 2))*Wd + tx0 + (q1 & 3);
            float i0 = sInv[q0], i1 = sInv[q1];
            float* o0 = g_att + (size_t)tok0*Cd + h*HDd + n0 + 2*t4;
            float* o1 = g_att + (size_t)tok1*Cd + h*HDd + n0 + 2*t4;
            o0[0] = c0  * i0; o0[1] = c1 * i0;
            o1[0] = c2v * i1; o1[1] = c3 * i1;
        }
    }
}

// ---------------- GroupNorm stats per (b, group) ----------------
__global__ void gn_stats_kernel() {
    int bg = blockIdx.x;
    int b = bg / GNg, g = bg % GNg;
    int tid = threadIdx.x;
    float sm = 0.f, sq = 0.f;
    for (int i = tid; i < HW*32; i += 256) {
        int ch  = g*32 + (i & 31);
        int pos = i >> 5;
        float v = g_h1[(size_t)(b*HW + pos)*HIDd + ch];
        sm += v; sq += v*v;
    }
    #pragma unroll
    for (int d = 16; d > 0; d >>= 1) {
        sm += __shfl_xor_sync(0xffffffffu, sm, d);
        sq += __shfl_xor_sync(0xffffffffu, sq, d);
    }
    __shared__ float s1[8], s2[8];
    int warp = tid >> 5, lane = tid & 31;
    if (lane == 0) { s1[warp] = sm; s2[warp] = sq; }
    __syncthreads();
    if (tid == 0) {
        float ss = 0.f, qq = 0.f;
        #pragma unroll
        for (int i = 0; i < 8; i++) { ss += s1[i]; qq += s2[i]; }
        float cnt = (float)(HW*32);
        float mu  = ss / cnt;
        float var = qq / cnt - mu*mu;
        g_gnm[bg*2]   = mu;
        g_gnm[bg*2+1] = rsqrtf(var + EPSf);
    }
}

// ---------------- fused GN + GELU + 5x5 depthwise conv ----------------
__global__ void dwconv_fused_kernel(const float* __restrict__ gg,
                                    const float* __restrict__ gb,
                                    const float* __restrict__ Wdw) {
    __shared__ float sT[144][68];

    int tileid = blockIdx.x;
    int cg = blockIdx.y, b = blockIdx.z;
    int ty0 = (tileid / 5) * 8, tx0 = (tileid % 5) * 8;
    int tid = threadIdx.x;
    int ch  = tid & 63;
    int chg = cg*64 + ch;

    float gamma = gg[chg], beta = gb[chg];
    int grp = chg >> 5;
    float mu = g_gnm[(b*GNg + grp)*2];
    float rs = g_gnm[(b*GNg + grp)*2 + 1];

    float wreg[25];
    #pragma unroll
    for (int i = 0; i < 25; i++) wreg[i] = Wdw[chg*25 + i];

    for (int i = tid; i < 144*64; i += 256) {
        int pos = i >> 6;
        int wy = pos / 12, wx = pos - (pos/12)*12;
        int y = ty0 + wy - 2, x = tx0 + wx - 2;
        float v = 0.f;
        if (y >= 0 && y < Hh && x >= 0 && x < Wd) {
            float hv = g_h1[(size_t)(b*HW + y*Wd + x)*HIDd + chg];
            hv = (hv - mu) * rs * gamma + beta;
            v = 0.5f * hv * (1.f + erff(hv * 0.70710678118654752f));
        }
        sT[pos][ch] = v;
    }
    __syncthreads();

    int pg = tid >> 6;
    #pragma unroll
    for (int p = 0; p < 16; p++) {
        int po = pg*16 + p;
        int y = po >> 3, x = po & 7;
        float acc = 0.f;
        #pragma unroll
        for (int dy = 0; dy < 5; dy++)
            #pragma unroll
            for (int dx = 0; dx < 5; dx++)
                acc += wreg[dy*5+dx] * sT[(y+dy)*12 + (x+dx)][ch];
        g_cv[(size_t)(b*HW + (ty0+y)*Wd + (tx0+x))*HIDd + chg] = acc;
    }
}

// ---------------- launch ----------------
extern "C" void kernel_launch(void* const* d_in, const int* in_sizes, int n_in,
                              void* d_out, int out_size) {
    const float* img   = (const float*)d_in[0];
    const float* imw   = (const float*)d_in[1];
    const float* msk   = (const float*)d_in[2];
    const float* ln1g  = (const float*)d_in[3];
    const float* ln1b  = (const float*)d_in[4];
    const float* ln2g  = (const float*)d_in[5];
    const float* ln2b  = (const float*)d_in[6];
    const float* Wq    = (const float*)d_in[7];
    const float* bq    = (const float*)d_in[8];
    const float* Wk    = (const float*)d_in[9];
    const float* bk    = (const float*)d_in[10];
    const float* Wv    = (const float*)d_in[11];
    const float* bv    = (const float*)d_in[12];
    const float* Wrel  = (const float*)d_in[13];
    const float* brel  = (const float*)d_in[14];
    const float* Wproj = (const float*)d_in[15];
    const float* bproj = (const float*)d_in[16];
    const float* W1    = (const float*)d_in[17];
    const float* bW1   = (const float*)d_in[18];
    const float* gng   = (const float*)d_in[19];
    const float* gnb   = (const float*)d_in[20];
    const float* Wdw   = (const float*)d_in[21];
    const float* W2    = (const float*)d_in[22];
    const float* bW2   = (const float*)d_in[23];
    float* out = (float*)d_out;

    float *qln, *kln, *vln, *Q, *K, *V, *att, *x1, *ln2, *h1, *cv;
    cudaGetSymbolAddress((void**)&qln, g_qln);
    cudaGetSymbolAddress((void**)&kln, g_kln);
    cudaGetSymbolAddress((void**)&vln, g_vln);
    cudaGetSymbolAddress((void**)&Q,   g_Q);
    cudaGetSymbolAddress((void**)&K,   g_K);
    cudaGetSymbolAddress((void**)&V,   g_V);
    cudaGetSymbolAddress((void**)&att, g_att);
    cudaGetSymbolAddress((void**)&x1,  g_x1);
    cudaGetSymbolAddress((void**)&ln2, g_ln2);
    cudaGetSymbolAddress((void**)&h1,  g_h1);
    cudaGetSymbolAddress((void**)&cv,  g_cv);

    int smem128 = (2*128*KP + 2*BN*KP) * sizeof(float);
    cudaFuncSetAttribute(mma_gemm_kernel<128>,
                         cudaFuncAttributeMaxDynamicSharedMemorySize, smem128);
    cudaFuncSetAttribute(mma_qkv_kernel,
                         cudaFuncAttributeMaxDynamicSharedMemorySize, smem128);

    // 1. LayerNorms
    ln3_kernel<<<TOK, 256>>>(img, imw, msk, ln1g, ln1b);

    // 2. QKV projections
    QKVArgs qa;
    qa.A[0] = qln; qa.A[1] = kln; qa.A[2] = vln;
    qa.W[0] = Wq;  qa.W[1] = Wk;  qa.W[2] = Wv;
    qa.bias[0] = bq; qa.bias[1] = bk; qa.bias[2] = bv;
    qa.C[0] = Q; qa.C[1] = K; qa.C[2] = V;
    mma_qkv_kernel<<<dim3(Cd/BN, TOK/128, 3), 256, smem128>>>(qa);

    // 3. tensor-core attention v4 (55.1KB smem -> 4 blocks/SM)
    int attn_smem = (16*PKW + NBIG + 512 + 16) * 4 + 16*SSB*2 + 16*RELB*2;
    cudaFuncSetAttribute(attn_tile_kernel,
                         cudaFuncAttributeMaxDynamicSharedMemorySize, attn_smem);
    attn_tile_kernel<<<dim3((Hh/QT)*(Wd/QT), NHd, Bz), 256, attn_smem>>>(Wrel, brel);

    // 4. output projection + fused residual -> x1
    mma_gemm_kernel<128><<<dim3(Cd/BN, TOK/128), 256, smem128>>>(att, Wproj, bproj, x1,
                                                                 Cd, Cd, 1, img);

    // 5. MLP branch
    ln_tok_kernel<<<TOK, 256>>>(ln2g, ln2b);
    mma_gemm_kernel<128><<<dim3(HIDd/BN, TOK/128), 256, smem128>>>(ln2, W1, bW1, h1,
                                                                   HIDd, Cd, 0, nullptr);
    gn_stats_kernel<<<Bz*GNg, 256>>>();
    dwconv_fused_kernel<<<dim3(25, HIDd/64, Bz), 256>>>(gng, gnb, Wdw);

    // 6. W2 + fused final residual + transpose to BCHW
    mma_gemm_kernel<128><<<dim3(Cd/BN, TOK/128), 256, smem128>>>(cv, W2, bW2, out,
                                                                 Cd, HIDd, 2, x1);
}